// round 1
// baseline (speedup 1.0000x reference)
#include <cuda_runtime.h>
#include <cstdint>

typedef unsigned long long ull;

#define NMOL 512
#define MA   64
#define F    128
#define NF   16
#define DIN  2176   // F*(1+NF)
#define HID  512

// ---------- packed f32x2 helpers (FFMA2 path: 2x fp32 rate on sm_103a) ----------
__device__ __forceinline__ ull pack2(float x, float y) {
    ull r; asm("mov.b64 %0, {%1,%2};" : "=l"(r) : "f"(x), "f"(y)); return r;
}
__device__ __forceinline__ void unpack2(ull v, float &x, float &y) {
    asm("mov.b64 {%0,%1}, %2;" : "=f"(x), "=f"(y) : "l"(v));
}
__device__ __forceinline__ void ffma2(ull &c, ull a, ull b) {
    asm("fma.rn.f32x2 %0, %1, %2, %3;" : "=l"(c) : "l"(a), "l"(b), "l"(c));
}

// ---------- scratch (device globals: allocation-free) ----------
__device__ float g_W[(size_t)NMOL * NF * MA * MA];   // 134 MB  RBF weights
__device__ float g_U[(size_t)NMOL * MA * NF * F];    // 268 MB  aggregated features
__device__ float g_T[(size_t)NMOL * MA * HID];       // 64 MB   hidden activations

// ---------- K0: copy z (as float) and r into the output buffer ----------
__global__ void k0_copy(const int* __restrict__ z, const float* __restrict__ r,
                        float* __restrict__ oz, float* __restrict__ orr,
                        int nz, int nr) {
    int i = blockIdx.x * blockDim.x + threadIdx.x;
    if (i < nz) oz[i]  = (float)z[i];
    if (i < nr) orr[i] = r[i];
}

// ---------- K1a: RBF weights w[n,f,a,b] = pm * 5*exp(-((d-mu_f)^2)/sigma_f) ----------
// Mask folded in by setting d of masked pairs to 1e9 (exp underflows to exactly 0).
__global__ __launch_bounds__(256) void k1a_rbf(
    const int* __restrict__ z, const float* __restrict__ r,
    const float* __restrict__ dist, const float* __restrict__ wid,
    float* __restrict__ Wout)
{
    __shared__ float sr[MA * 3];
    __shared__ float sm[MA];
    __shared__ float smu[NF], sis[NF];
    int n = blockIdx.x, tid = threadIdx.x;

    for (int i = tid; i < MA * 3; i += 256) sr[i] = r[(size_t)n * MA * 3 + i];
    if (tid < MA) sm[tid] = (z[n * MA + tid] > -1) ? 1.0f : 0.0f;
    if (tid < NF) { smu[tid] = dist[tid]; sis[tid] = 1.0f / wid[tid]; }
    __syncthreads();

    float d[16];
#pragma unroll
    for (int q = 0; q < 16; q++) {
        int p = tid + q * 256;
        int a = p >> 6, b = p & 63;
        float dx = sr[a * 3 + 0] - sr[b * 3 + 0];
        float dy = sr[a * 3 + 1] - sr[b * 3 + 1];
        float dz = sr[a * 3 + 2] - sr[b * 3 + 2];
        float dd = sqrtf(dx * dx + dy * dy + dz * dz + 1e-12f);
        if (sm[a] * sm[b] == 0.0f) dd = 1e9f;
        d[q] = dd;
    }
    float* Wn = Wout + (size_t)n * NF * MA * MA;
    for (int f = 0; f < NF; f++) {
        float mu = smu[f], isg = sis[f];
#pragma unroll
        for (int q = 0; q < 16; q++) {
            float t = d[q] - mu;
            Wn[f * (MA * MA) + tid + q * 256] = 5.0f * expf(-t * t * isg);
        }
    }
}

// ---------- K1b: u[n,a,f*F+c] = sum_b w[n,f,a,b] * h[n,b,c] ----------
// One block per molecule. h tile (32KB) + one w tile (16KB) in smem = 48KB exactly.
__global__ __launch_bounds__(256) void k1b_agg(
    const float* __restrict__ h, const float* __restrict__ Wg, float* __restrict__ U)
{
    __shared__ float sh_h[MA * F];    // 32 KB
    __shared__ float sh_w[MA * MA];   // 16 KB
    int n = blockIdx.x, tid = threadIdx.x;

    {
        const float4* hg = (const float4*)(h + (size_t)n * MA * F);
        float4* hs = (float4*)sh_h;
        for (int i = tid; i < MA * F / 4; i += 256) hs[i] = hg[i];
    }
    int tm = tid >> 4, tn = tid & 15;
    int a0 = tm * 4, c0 = tn * 8;
    const float* Wn = Wg + (size_t)n * NF * MA * MA;
    float* Un = U + (size_t)n * MA * (NF * F);
    __syncthreads();

    for (int f = 0; f < NF; f++) {
        // stage w_f
        {
            const float4* wg = (const float4*)(Wn + f * (MA * MA));
            float4* ws = (float4*)sh_w;
#pragma unroll
            for (int q = 0; q < 4; q++) ws[tid + q * 256] = wg[tid + q * 256];
        }
        __syncthreads();

        ull acc[4][4];
#pragma unroll
        for (int i = 0; i < 4; i++)
#pragma unroll
            for (int j = 0; j < 4; j++) acc[i][j] = 0ull;

#pragma unroll 4
        for (int b = 0; b < MA; b++) {
            float4 h0 = *(const float4*)&sh_h[b * F + c0];
            float4 h1 = *(const float4*)&sh_h[b * F + c0 + 4];
            ull hp[4] = { pack2(h0.x, h0.y), pack2(h0.z, h0.w),
                          pack2(h1.x, h1.y), pack2(h1.z, h1.w) };
#pragma unroll
            for (int i = 0; i < 4; i++) {
                float wv = sh_w[(a0 + i) * MA + b];
                ull wd = pack2(wv, wv);
#pragma unroll
                for (int j = 0; j < 4; j++) ffma2(acc[i][j], wd, hp[j]);
            }
        }
#pragma unroll
        for (int i = 0; i < 4; i++) {
            float o[8];
#pragma unroll
            for (int j = 0; j < 4; j++) unpack2(acc[i][j], o[2 * j], o[2 * j + 1]);
            float4* dst = (float4*)&Un[(size_t)(a0 + i) * (NF * F) + f * F + c0];
            dst[0] = make_float4(o[0], o[1], o[2], o[3]);
            dst[1] = make_float4(o[4], o[5], o[6], o[7]);
        }
        __syncthreads();
    }
}

// ---------- K2: T = silu([h|U] @ W1 + b1), 32768 x 2176 x 512 ----------
__global__ __launch_bounds__(256) void k2_gemm1(
    const float* __restrict__ h, const float* __restrict__ U,
    const float* __restrict__ W1, const float* __restrict__ b1,
    float* __restrict__ T)
{
    __shared__ float As[16][132];
    __shared__ float Bs[16][128];
    int bn = blockIdx.x, bm = blockIdx.y;
    int row0 = bm * 128, col0 = bn * 128;
    int tid = threadIdx.x;
    int tm = tid >> 4, tn = tid & 15;

    ull acc[4][8];
#pragma unroll
    for (int i = 0; i < 4; i++)
#pragma unroll
        for (int j = 0; j < 8; j++) acc[i][j] = 0ull;

    for (int kt = 0; kt < DIN / 16; kt++) {
        int k0 = kt * 16;
        const float* Ab; int lda;
        if (k0 < F) { Ab = h + (size_t)row0 * F + k0;              lda = F; }
        else        { Ab = U + (size_t)row0 * (NF * F) + (k0 - F); lda = NF * F; }
#pragma unroll
        for (int q = 0; q < 2; q++) {
            int v = tid * 2 + q;
            int i = v >> 2, kk = (v & 3) * 4;
            float4 av = *(const float4*)(Ab + (size_t)i * lda + kk);
            As[kk + 0][i] = av.x; As[kk + 1][i] = av.y;
            As[kk + 2][i] = av.z; As[kk + 3][i] = av.w;
        }
#pragma unroll
        for (int q = 0; q < 2; q++) {
            int v = tid * 2 + q;
            int kk = v >> 5, j = (v & 31) * 4;
            *(float4*)&Bs[kk][j] = *(const float4*)(W1 + (size_t)(k0 + kk) * HID + col0 + j);
        }
        __syncthreads();
#pragma unroll
        for (int kk = 0; kk < 16; kk++) {
            float4 a0v = *(const float4*)&As[kk][tm * 8];
            float4 a1v = *(const float4*)&As[kk][tm * 8 + 4];
            ull ap[4] = { pack2(a0v.x, a0v.y), pack2(a0v.z, a0v.w),
                          pack2(a1v.x, a1v.y), pack2(a1v.z, a1v.w) };
            float4 b0v = *(const float4*)&Bs[kk][tn * 8];
            float4 b1v = *(const float4*)&Bs[kk][tn * 8 + 4];
            float bs[8] = { b0v.x, b0v.y, b0v.z, b0v.w, b1v.x, b1v.y, b1v.z, b1v.w };
#pragma unroll
            for (int j = 0; j < 8; j++) {
                ull bd = pack2(bs[j], bs[j]);
#pragma unroll
                for (int i = 0; i < 4; i++) ffma2(acc[i][j], ap[i], bd);
            }
        }
        __syncthreads();
    }
    // epilogue: bias + silu, pairs are adjacent rows
    float4 bb0 = *(const float4*)&b1[col0 + tn * 8];
    float4 bb1 = *(const float4*)&b1[col0 + tn * 8 + 4];
    float bv[8] = { bb0.x, bb0.y, bb0.z, bb0.w, bb1.x, bb1.y, bb1.z, bb1.w };
#pragma unroll
    for (int i = 0; i < 4; i++) {
        int rr = row0 + tm * 8 + 2 * i;
        float lo[8], hi[8];
#pragma unroll
        for (int j = 0; j < 8; j++) {
            unpack2(acc[i][j], lo[j], hi[j]);
            float x0 = lo[j] + bv[j], x1 = hi[j] + bv[j];
            lo[j] = x0 / (1.0f + expf(-x0));
            hi[j] = x1 / (1.0f + expf(-x1));
        }
        float4* d0 = (float4*)&T[(size_t)rr * HID + col0 + tn * 8];
        float4* d1 = (float4*)&T[(size_t)(rr + 1) * HID + col0 + tn * 8];
        d0[0] = make_float4(lo[0], lo[1], lo[2], lo[3]);
        d0[1] = make_float4(lo[4], lo[5], lo[6], lo[7]);
        d1[0] = make_float4(hi[0], hi[1], hi[2], hi[3]);
        d1[1] = make_float4(hi[4], hi[5], hi[6], hi[7]);
    }
}

// ---------- K3: out = h + 0.1 * (T @ W2 + b2) * mask ----------
__global__ __launch_bounds__(256) void k3_gemm2(
    const float* __restrict__ T, const float* __restrict__ W2,
    const float* __restrict__ b2, const float* __restrict__ h,
    const int* __restrict__ z, float* __restrict__ out)
{
    __shared__ float As[16][132];
    __shared__ float Bs[16][128];
    int bm = blockIdx.x;
    int row0 = bm * 128;
    int tid = threadIdx.x;
    int tm = tid >> 4, tn = tid & 15;

    ull acc[4][8];
#pragma unroll
    for (int i = 0; i < 4; i++)
#pragma unroll
        for (int j = 0; j < 8; j++) acc[i][j] = 0ull;

    for (int kt = 0; kt < HID / 16; kt++) {
        int k0 = kt * 16;
        const float* Ab = T + (size_t)row0 * HID + k0;
#pragma unroll
        for (int q = 0; q < 2; q++) {
            int v = tid * 2 + q;
            int i = v >> 2, kk = (v & 3) * 4;
            float4 av = *(const float4*)(Ab + (size_t)i * HID + kk);
            As[kk + 0][i] = av.x; As[kk + 1][i] = av.y;
            As[kk + 2][i] = av.z; As[kk + 3][i] = av.w;
        }
#pragma unroll
        for (int q = 0; q < 2; q++) {
            int v = tid * 2 + q;
            int kk = v >> 5, j = (v & 31) * 4;
            *(float4*)&Bs[kk][j] = *(const float4*)(W2 + (size_t)(k0 + kk) * F + j);
        }
        __syncthreads();
#pragma unroll
        for (int kk = 0; kk < 16; kk++) {
            float4 a0v = *(const float4*)&As[kk][tm * 8];
            float4 a1v = *(const float4*)&As[kk][tm * 8 + 4];
            ull ap[4] = { pack2(a0v.x, a0v.y), pack2(a0v.z, a0v.w),
                          pack2(a1v.x, a1v.y), pack2(a1v.z, a1v.w) };
            float4 b0v = *(const float4*)&Bs[kk][tn * 8];
            float4 b1v = *(const float4*)&Bs[kk][tn * 8 + 4];
            float bs[8] = { b0v.x, b0v.y, b0v.z, b0v.w, b1v.x, b1v.y, b1v.z, b1v.w };
#pragma unroll
            for (int j = 0; j < 8; j++) {
                ull bd = pack2(bs[j], bs[j]);
#pragma unroll
                for (int i = 0; i < 4; i++) ffma2(acc[i][j], ap[i], bd);
            }
        }
        __syncthreads();
    }
    float4 bb0 = *(const float4*)&b2[tn * 8];
    float4 bb1 = *(const float4*)&b2[tn * 8 + 4];
    float bv[8] = { bb0.x, bb0.y, bb0.z, bb0.w, bb1.x, bb1.y, bb1.z, bb1.w };
#pragma unroll
    for (int i = 0; i < 4; i++) {
        int rr = row0 + tm * 8 + 2 * i;
        float mlo = (z[rr] > -1)     ? 0.1f : 0.0f;
        float mhi = (z[rr + 1] > -1) ? 0.1f : 0.0f;
        float lo[8], hi[8];
#pragma unroll
        for (int j = 0; j < 8; j++) unpack2(acc[i][j], lo[j], hi[j]);
        float4 h00 = *(const float4*)&h[(size_t)rr * F + tn * 8];
        float4 h01 = *(const float4*)&h[(size_t)rr * F + tn * 8 + 4];
        float4 h10 = *(const float4*)&h[(size_t)(rr + 1) * F + tn * 8];
        float4 h11 = *(const float4*)&h[(size_t)(rr + 1) * F + tn * 8 + 4];
        float hl[8] = { h00.x, h00.y, h00.z, h00.w, h01.x, h01.y, h01.z, h01.w };
        float hh[8] = { h10.x, h10.y, h10.z, h10.w, h11.x, h11.y, h11.z, h11.w };
#pragma unroll
        for (int j = 0; j < 8; j++) {
            lo[j] = hl[j] + mlo * (lo[j] + bv[j]);
            hi[j] = hh[j] + mhi * (hi[j] + bv[j]);
        }
        float4* d0 = (float4*)&out[(size_t)rr * F + tn * 8];
        float4* d1 = (float4*)&out[(size_t)(rr + 1) * F + tn * 8];
        d0[0] = make_float4(lo[0], lo[1], lo[2], lo[3]);
        d0[1] = make_float4(lo[4], lo[5], lo[6], lo[7]);
        d1[0] = make_float4(hi[0], hi[1], hi[2], hi[3]);
        d1[1] = make_float4(hi[4], hi[5], hi[6], hi[7]);
    }
}

extern "C" void kernel_launch(void* const* d_in, const int* in_sizes, int n_in,
                              void* d_out, int out_size)
{
    const int*   z    = (const int*)d_in[0];
    const float* r    = (const float*)d_in[1];
    const float* h    = (const float*)d_in[2];
    const float* dist = (const float*)d_in[3];
    const float* wid  = (const float*)d_in[4];
    const float* W1   = (const float*)d_in[5];
    const float* b1   = (const float*)d_in[6];
    const float* W2   = (const float*)d_in[7];
    const float* b2   = (const float*)d_in[8];

    float *Wsc, *U, *T;
    cudaGetSymbolAddress((void**)&Wsc, g_W);
    cudaGetSymbolAddress((void**)&U,   g_U);
    cudaGetSymbolAddress((void**)&T,   g_T);

    int nz = in_sizes[0], nr = in_sizes[1], nh = in_sizes[2];
    int nmol = nh / (MA * F);            // 512
    int rows = nmol * MA;                // 32768

    float* out   = (float*)d_out;
    float* out_h = out;
    if (out_size == nz + nr + nh) {
        // output = concat(z as float, r, h_new)
        k0_copy<<<(nr + 255) / 256, 256>>>(z, r, out, out + nz, nz, nr);
        out_h = out + nz + nr;
    }

    k1a_rbf<<<nmol, 256>>>(z, r, dist, wid, Wsc);
    k1b_agg<<<nmol, 256>>>(h, Wsc, U);
    dim3 g2(HID / 128, rows / 128);
    k2_gemm1<<<g2, 256>>>(h, U, W1, b1, T);
    k3_gemm2<<<rows / 128, 256>>>(T, W2, b2, h, z, out_h);
}

// round 5
// speedup vs baseline: 2.3284x; 2.3284x over previous
#include <cuda_runtime.h>
#include <cstdint>

typedef unsigned long long ull;

#define NMOL 512
#define MA   64
#define F    128
#define NF   16
#define DIN  2176   // F*(1+NF)
#define HID  512

// ======================= helpers =======================
__device__ __forceinline__ uint32_t smem_to_u32(const void* p) {
    uint32_t a;
    asm("{ .reg .u64 t; cvta.to.shared.u64 t, %1; cvt.u32.u64 %0, t; }" : "=r"(a) : "l"(p));
    return a;
}
__device__ __forceinline__ void cpasync16(uint32_t s, const void* g) {
    asm volatile("cp.async.cg.shared.global [%0], [%1], 16;" :: "r"(s), "l"(g) : "memory");
}
__device__ __forceinline__ void cp_commit() { asm volatile("cp.async.commit_group;" ::: "memory"); }
__device__ __forceinline__ void cp_wait1()  { asm volatile("cp.async.wait_group 1;"  ::: "memory"); }
__device__ __forceinline__ void cp_wait0()  { asm volatile("cp.async.wait_group 0;"  ::: "memory"); }

// Ampere-style tf32 MMA: D(f32) += A(tf32) * B(tf32), m16n8k8
__device__ __forceinline__ void mma8(float& c0, float& c1, float& c2, float& c3,
                                     uint32_t a0, uint32_t a1, uint32_t a2, uint32_t a3,
                                     uint32_t b0, uint32_t b1) {
    asm volatile("mma.sync.aligned.m16n8k8.row.col.f32.tf32.tf32.f32 "
                 "{%0,%1,%2,%3}, {%4,%5,%6,%7}, {%8,%9}, {%0,%1,%2,%3};"
                 : "+f"(c0), "+f"(c1), "+f"(c2), "+f"(c3)
                 : "r"(a0), "r"(a1), "r"(a2), "r"(a3), "r"(b0), "r"(b1));
}

// ---------- packed f32x2 helpers ----------
__device__ __forceinline__ ull pack2(float x, float y) {
    ull r; asm("mov.b64 %0, {%1,%2};" : "=l"(r) : "f"(x), "f"(y)); return r;
}
__device__ __forceinline__ void unpack2(ull v, float &x, float &y) {
    asm("mov.b64 {%0,%1}, %2;" : "=f"(x), "=f"(y) : "l"(v));
}
__device__ __forceinline__ void ffma2(ull &c, ull a, ull b) {
    asm("fma.rn.f32x2 %0, %1, %2, %3;" : "=l"(c) : "l"(a), "l"(b), "l"(c));
}

// ---------- scratch (device globals: allocation-free) ----------
__device__ float g_U[(size_t)NMOL * MA * NF * F];    // 268 MB  aggregated features
__device__ float g_T[(size_t)NMOL * MA * HID];       // 64 MB   hidden activations
__device__ float g_Bt[(size_t)HID * DIN];            // 4.5 MB  W1^T [512 x 2176]
__device__ float g_W2t[(size_t)F * HID];             // 256 KB  W2^T [128 x 512]

// ---------- K0: copy z (as float) and r into the output buffer ----------
__global__ void k0_copy(const int* __restrict__ z, const float* __restrict__ r,
                        float* __restrict__ oz, float* __restrict__ orr,
                        int nz, int nr) {
    int i = blockIdx.x * blockDim.x + threadIdx.x;
    if (i < nz) oz[i]  = (float)z[i];
    if (i < nr) orr[i] = r[i];
}

// ---------- K_tr: dst[n,k] = src[k,n], src is [K x N] row-major ----------
__global__ void k_trg(const float* __restrict__ src, float* __restrict__ dst,
                      int K, int N) {
    __shared__ float t[32][33];
    int kx = blockIdx.x * 32, ny = blockIdx.y * 32;
    int tx = threadIdx.x, ty = threadIdx.y;
#pragma unroll
    for (int i = 0; i < 32; i += 8)
        t[ty + i][tx] = src[(size_t)(kx + ty + i) * N + ny + tx];
    __syncthreads();
#pragma unroll
    for (int i = 0; i < 32; i += 8)
        dst[(size_t)(ny + ty + i) * K + kx + tx] = t[tx][ty + i];
}

// ---------- K1 fused: RBF weights + neighbor aggregation (FFMA2) ----------
__global__ __launch_bounds__(256) void k1_fused(
    const int* __restrict__ z, const float* __restrict__ r,
    const float* __restrict__ dist, const float* __restrict__ widths,
    const float* __restrict__ h, float* __restrict__ U)
{
    __shared__ float sh_h[MA * F];    // 32 KB
    __shared__ float sh_w[MA * MA];   // 16 KB (temp: r + mask, then w_f tiles)
    int n = blockIdx.x, tid = threadIdx.x;

    {
        const float4* hg = (const float4*)(h + (size_t)n * MA * F);
        float4* hs = (float4*)sh_h;
        for (int i = tid; i < MA * F / 4; i += 256) hs[i] = hg[i];
    }
    float* tr  = sh_w;         // 192 floats
    float* msk = sh_w + 192;   // 64 floats
    if (tid < 192) tr[tid] = r[(size_t)n * MA * 3 + tid];
    if (tid >= 192 && tid < 256) msk[tid - 192] = (z[n * MA + (tid - 192)] > -1) ? 1.0f : 0.0f;
    __syncthreads();

    float d[16];
#pragma unroll
    for (int q = 0; q < 16; q++) {
        int p = tid + q * 256;
        int a = p >> 6, b = p & 63;
        float dx = tr[a * 3 + 0] - tr[b * 3 + 0];
        float dy = tr[a * 3 + 1] - tr[b * 3 + 1];
        float dz = tr[a * 3 + 2] - tr[b * 3 + 2];
        float dd = sqrtf(dx * dx + dy * dy + dz * dz + 1e-12f);
        if (msk[a] * msk[b] == 0.0f) dd = 1e9f;
        d[q] = dd;
    }
    __syncthreads();

    int tm = tid >> 4, tn = tid & 15;
    int a0 = tm * 4, c0 = tn * 8;
    float* Un = U + (size_t)n * MA * (NF * F);

    for (int f = 0; f < NF; f++) {
        float mu  = __ldg(&dist[f]);
        float isg = 1.0f / __ldg(&widths[f]);
#pragma unroll
        for (int q = 0; q < 16; q++) {
            float t = d[q] - mu;
            sh_w[tid + q * 256] = 5.0f * expf(-t * t * isg);
        }
        __syncthreads();

        ull acc[4][4];
#pragma unroll
        for (int i = 0; i < 4; i++)
#pragma unroll
            for (int j = 0; j < 4; j++) acc[i][j] = 0ull;

#pragma unroll 4
        for (int b = 0; b < MA; b++) {
            float4 h0 = *(const float4*)&sh_h[b * F + c0];
            float4 h1 = *(const float4*)&sh_h[b * F + c0 + 4];
            ull hp[4] = { pack2(h0.x, h0.y), pack2(h0.z, h0.w),
                          pack2(h1.x, h1.y), pack2(h1.z, h1.w) };
#pragma unroll
            for (int i = 0; i < 4; i++) {
                float wv = sh_w[(a0 + i) * MA + b];
                ull wd = pack2(wv, wv);
#pragma unroll
                for (int j = 0; j < 4; j++) ffma2(acc[i][j], wd, hp[j]);
            }
        }
#pragma unroll
        for (int i = 0; i < 4; i++) {
            float o[8];
#pragma unroll
            for (int j = 0; j < 4; j++) unpack2(acc[i][j], o[2 * j], o[2 * j + 1]);
            float4* dst = (float4*)&Un[(size_t)(a0 + i) * (NF * F) + f * F + c0];
            dst[0] = make_float4(o[0], o[1], o[2], o[3]);
            dst[1] = make_float4(o[4], o[5], o[6], o[7]);
        }
        __syncthreads();
    }
}

// ======================= K2: T = silu([h|U] @ W1 + b1) via mma.sync tf32 =======================
// BM=128, BN=256, BK=32, 3-stage cp.async. 8 warps: 2(m) x 4(n), warp tile 64x64.
// smem rows padded to stride 36 floats (36 mod 32 == 4 -> conflict-free frag LDS).
#define K2_CHUNKS 68
#define K2_A_BYTES (128 * 36 * 4)              // 18432
#define K2_B_BYTES (256 * 36 * 4)              // 36864
#define K2_STAGE   (K2_A_BYTES + K2_B_BYTES)   // 55296
#define K2_DYN     (3 * K2_STAGE)              // 165888

__device__ __forceinline__ void k2_load(int j, int row0, int col0,
    const float* __restrict__ h, const float* __restrict__ U,
    const float* __restrict__ Bt, uint32_t sA, uint32_t sB, int tid)
{
    int k0 = j * 32;
    const float* Ab; size_t lda;
    if (k0 < F) { Ab = h + (size_t)row0 * F + k0;          lda = F; }
    else        { Ab = U + (size_t)row0 * 2048 + (k0 - F); lda = 2048; }
#pragma unroll
    for (int p = 0; p < 4; p++) {
        int idx = p * 256 + tid;
        int m = idx >> 3, kq = idx & 7;
        cpasync16(sA + m * 144 + kq * 16, Ab + (size_t)m * lda + kq * 4);
    }
    const float* Bb = Bt + (size_t)col0 * DIN + k0;
#pragma unroll
    for (int p = 0; p < 8; p++) {
        int idx = p * 256 + tid;
        int nn = idx >> 3, kq = idx & 7;
        cpasync16(sB + nn * 144 + kq * 16, Bb + (size_t)nn * DIN + kq * 4);
    }
}

__global__ __launch_bounds__(256, 1) void k2_tc(
    const float* __restrict__ h, const float* __restrict__ U,
    const float* __restrict__ Bt, const float* __restrict__ b1,
    float* __restrict__ T)
{
    extern __shared__ float dynf[];
    uint32_t dbase = smem_to_u32(dynf);
    int tid = threadIdx.x, wid = tid >> 5, lane = tid & 31;
    int gid = lane >> 2, tig = lane & 3;
    int warp_m = wid >> 2, warp_n = wid & 3;
    int col0 = blockIdx.x * 256, row0 = blockIdx.y * 128;

    float acc[4][8][4];
#pragma unroll
    for (int mf = 0; mf < 4; mf++)
#pragma unroll
        for (int nf = 0; nf < 8; nf++)
#pragma unroll
            for (int q = 0; q < 4; q++) acc[mf][nf][q] = 0.0f;

    // prologue: 2 stages in flight
    k2_load(0, row0, col0, h, U, Bt, dbase, dbase + K2_A_BYTES, tid);
    cp_commit();
    k2_load(1, row0, col0, h, U, Bt, dbase + K2_STAGE, dbase + K2_STAGE + K2_A_BYTES, tid);
    cp_commit();

    for (int j = 0; j < K2_CHUNKS; j++) {
        int s = j % 3;
        if (j < K2_CHUNKS - 1) cp_wait1(); else cp_wait0();
        __syncthreads();
        if (j + 2 < K2_CHUNKS) {
            int s2 = (j + 2) % 3;
            k2_load(j + 2, row0, col0, h, U, Bt,
                    dbase + s2 * K2_STAGE, dbase + s2 * K2_STAGE + K2_A_BYTES, tid);
            cp_commit();
        }
        const float* sA = dynf + (s * K2_STAGE) / 4;
        const float* sB = sA + K2_A_BYTES / 4;
#pragma unroll
        for (int kk = 0; kk < 4; kk++) {
            int k = kk * 8 + tig;
            uint32_t a[4][4];
#pragma unroll
            for (int mf = 0; mf < 4; mf++) {
                const float* ap = sA + (warp_m * 64 + mf * 16 + gid) * 36 + k;
                a[mf][0] = __float_as_uint(ap[0]);
                a[mf][1] = __float_as_uint(ap[8 * 36]);
                a[mf][2] = __float_as_uint(ap[4]);
                a[mf][3] = __float_as_uint(ap[8 * 36 + 4]);
            }
#pragma unroll
            for (int nf = 0; nf < 8; nf++) {
                const float* bp = sB + (warp_n * 64 + nf * 8 + gid) * 36 + k;
                uint32_t b0 = __float_as_uint(bp[0]);
                uint32_t b1r = __float_as_uint(bp[4]);
#pragma unroll
                for (int mf = 0; mf < 4; mf++)
                    mma8(acc[mf][nf][0], acc[mf][nf][1], acc[mf][nf][2], acc[mf][nf][3],
                         a[mf][0], a[mf][1], a[mf][2], a[mf][3], b0, b1r);
            }
        }
        __syncthreads();
    }

    // epilogue: bias + silu -> T
#pragma unroll
    for (int mf = 0; mf < 4; mf++) {
        int rr = row0 + warp_m * 64 + mf * 16 + gid;
#pragma unroll
        for (int nf = 0; nf < 8; nf++) {
            int cc = col0 + warp_n * 64 + nf * 8 + tig * 2;
            float ba = __ldg(&b1[cc]), bb = __ldg(&b1[cc + 1]);
            float x0 = acc[mf][nf][0] + ba, x1 = acc[mf][nf][1] + bb;
            float x2 = acc[mf][nf][2] + ba, x3 = acc[mf][nf][3] + bb;
            x0 = x0 / (1.0f + __expf(-x0));
            x1 = x1 / (1.0f + __expf(-x1));
            x2 = x2 / (1.0f + __expf(-x2));
            x3 = x3 / (1.0f + __expf(-x3));
            *(float2*)&T[(size_t)rr * HID + cc]       = make_float2(x0, x1);
            *(float2*)&T[(size_t)(rr + 8) * HID + cc] = make_float2(x2, x3);
        }
    }
}

// ======================= K3: out = h + 0.1*(T @ W2 + b2)*mask via mma.sync tf32 =======================
// BM=128, BN=128, BK=32, 3-stage. 8 warps: 2(m) x 4(n), warp tile 64x32.
#define K3_CHUNKS 16
#define K3_A_BYTES (128 * 36 * 4)              // 18432
#define K3_B_BYTES (128 * 36 * 4)              // 18432
#define K3_STAGE   (K3_A_BYTES + K3_B_BYTES)   // 36864
#define K3_DYN     (3 * K3_STAGE)              // 110592

__device__ __forceinline__ void k3_load(int j, int row0,
    const float* __restrict__ T, const float* __restrict__ W2t,
    uint32_t sA, uint32_t sB, int tid)
{
    int k0 = j * 32;
    const float* Ab = T + (size_t)row0 * HID + k0;
#pragma unroll
    for (int p = 0; p < 4; p++) {
        int idx = p * 256 + tid;
        int m = idx >> 3, kq = idx & 7;
        cpasync16(sA + m * 144 + kq * 16, Ab + (size_t)m * HID + kq * 4);
    }
    const float* Bb = W2t + k0;
#pragma unroll
    for (int p = 0; p < 4; p++) {
        int idx = p * 256 + tid;
        int nn = idx >> 3, kq = idx & 7;
        cpasync16(sB + nn * 144 + kq * 16, Bb + (size_t)nn * HID + kq * 4);
    }
}

__global__ __launch_bounds__(256, 1) void k3_tc(
    const float* __restrict__ T, const float* __restrict__ W2t,
    const float* __restrict__ b2, const float* __restrict__ h,
    const int* __restrict__ z, float* __restrict__ out)
{
    extern __shared__ float dynf[];
    uint32_t dbase = smem_to_u32(dynf);
    int tid = threadIdx.x, wid = tid >> 5, lane = tid & 31;
    int gid = lane >> 2, tig = lane & 3;
    int warp_m = wid >> 2, warp_n = wid & 3;
    int row0 = blockIdx.x * 128;

    float acc[4][4][4];
#pragma unroll
    for (int mf = 0; mf < 4; mf++)
#pragma unroll
        for (int nf = 0; nf < 4; nf++)
#pragma unroll
            for (int q = 0; q < 4; q++) acc[mf][nf][q] = 0.0f;

    k3_load(0, row0, T, W2t, dbase, dbase + K3_A_BYTES, tid);
    cp_commit();
    k3_load(1, row0, T, W2t, dbase + K3_STAGE, dbase + K3_STAGE + K3_A_BYTES, tid);
    cp_commit();

    for (int j = 0; j < K3_CHUNKS; j++) {
        int s = j % 3;
        if (j < K3_CHUNKS - 1) cp_wait1(); else cp_wait0();
        __syncthreads();
        if (j + 2 < K3_CHUNKS) {
            int s2 = (j + 2) % 3;
            k3_load(j + 2, row0, T, W2t,
                    dbase + s2 * K3_STAGE, dbase + s2 * K3_STAGE + K3_A_BYTES, tid);
            cp_commit();
        }
        const float* sA = dynf + (s * K3_STAGE) / 4;
        const float* sB = sA + K3_A_BYTES / 4;
#pragma unroll
        for (int kk = 0; kk < 4; kk++) {
            int k = kk * 8 + tig;
            uint32_t a[4][4];
#pragma unroll
            for (int mf = 0; mf < 4; mf++) {
                const float* ap = sA + (warp_m * 64 + mf * 16 + gid) * 36 + k;
                a[mf][0] = __float_as_uint(ap[0]);
                a[mf][1] = __float_as_uint(ap[8 * 36]);
                a[mf][2] = __float_as_uint(ap[4]);
                a[mf][3] = __float_as_uint(ap[8 * 36 + 4]);
            }
#pragma unroll
            for (int nf = 0; nf < 4; nf++) {
                const float* bp = sB + (warp_n * 32 + nf * 8 + gid) * 36 + k;
                uint32_t b0 = __float_as_uint(bp[0]);
                uint32_t b1r = __float_as_uint(bp[4]);
#pragma unroll
                for (int mf = 0; mf < 4; mf++)
                    mma8(acc[mf][nf][0], acc[mf][nf][1], acc[mf][nf][2], acc[mf][nf][3],
                         a[mf][0], a[mf][1], a[mf][2], a[mf][3], b0, b1r);
            }
        }
        __syncthreads();
    }

    // epilogue: residual + mask
#pragma unroll
    for (int mf = 0; mf < 4; mf++) {
        int rr = row0 + warp_m * 64 + mf * 16 + gid;
        float m0 = (__ldg(&z[rr])     > -1) ? 0.1f : 0.0f;
        float m8 = (__ldg(&z[rr + 8]) > -1) ? 0.1f : 0.0f;
#pragma unroll
        for (int nf = 0; nf < 4; nf++) {
            int cc = warp_n * 32 + nf * 8 + tig * 2;
            float ba = __ldg(&b2[cc]), bb = __ldg(&b2[cc + 1]);
            float2 h0 = *(const float2*)&h[(size_t)rr * F + cc];
            float2 h8 = *(const float2*)&h[(size_t)(rr + 8) * F + cc];
            float o0 = h0.x + m0 * (acc[mf][nf][0] + ba);
            float o1 = h0.y + m0 * (acc[mf][nf][1] + bb);
            float o2 = h8.x + m8 * (acc[mf][nf][2] + ba);
            float o3 = h8.y + m8 * (acc[mf][nf][3] + bb);
            *(float2*)&out[(size_t)rr * F + cc]       = make_float2(o0, o1);
            *(float2*)&out[(size_t)(rr + 8) * F + cc] = make_float2(o2, o3);
        }
    }
}

extern "C" void kernel_launch(void* const* d_in, const int* in_sizes, int n_in,
                              void* d_out, int out_size)
{
    const int*   z    = (const int*)d_in[0];
    const float* r    = (const float*)d_in[1];
    const float* h    = (const float*)d_in[2];
    const float* dist = (const float*)d_in[3];
    const float* wids = (const float*)d_in[4];
    const float* W1   = (const float*)d_in[5];
    const float* b1   = (const float*)d_in[6];
    const float* W2   = (const float*)d_in[7];
    const float* b2   = (const float*)d_in[8];

    float *U, *T, *Bt, *W2t;
    cudaGetSymbolAddress((void**)&U,   g_U);
    cudaGetSymbolAddress((void**)&T,   g_T);
    cudaGetSymbolAddress((void**)&Bt,  g_Bt);
    cudaGetSymbolAddress((void**)&W2t, g_W2t);

    int nz = in_sizes[0], nr = in_sizes[1], nh = in_sizes[2];
    int nmol = nh / (MA * F);            // 512
    int rows = nmol * MA;                // 32768

    float* out   = (float*)d_out;
    float* out_h = out;
    if (out_size == nz + nr + nh) {
        k0_copy<<<(nr + 255) / 256, 256>>>(z, r, out, out + nz, nz, nr);
        out_h = out + nz + nr;
    }

    k1_fused<<<nmol, 256>>>(z, r, dist, wids, h, U);
    k_trg<<<dim3(DIN / 32, HID / 32), dim3(32, 8)>>>(W1, Bt, DIN, HID);
    k_trg<<<dim3(HID / 32, F / 32), dim3(32, 8)>>>(W2, W2t, HID, F);

    cudaFuncSetAttribute(k2_tc, cudaFuncAttributeMaxDynamicSharedMemorySize, K2_DYN);
    k2_tc<<<dim3(HID / 256, rows / 128), 256, K2_DYN>>>(h, U, Bt, b1, T);

    cudaFuncSetAttribute(k3_tc, cudaFuncAttributeMaxDynamicSharedMemorySize, K3_DYN);
    k3_tc<<<rows / 128, 256, K3_DYN>>>(T, W2t, b2, h, z, out_h);
}

// round 6
// speedup vs baseline: 3.6536x; 1.5691x over previous
#include <cuda_runtime.h>
#include <cuda_fp16.h>
#include <cstdint>

typedef unsigned long long ull;

#define NMOL 512
#define MA   64
#define F    128
#define NF   16
#define DIN  2176   // F*(1+NF)
#define HID  512

// ======================= helpers =======================
__device__ __forceinline__ uint32_t smem_to_u32(const void* p) {
    uint32_t a;
    asm("{ .reg .u64 t; cvta.to.shared.u64 t, %1; cvt.u32.u64 %0, t; }" : "=r"(a) : "l"(p));
    return a;
}
__device__ __forceinline__ void cpasync16(uint32_t s, const void* g) {
    asm volatile("cp.async.cg.shared.global [%0], [%1], 16;" :: "r"(s), "l"(g) : "memory");
}
__device__ __forceinline__ void cp_commit() { asm volatile("cp.async.commit_group;" ::: "memory"); }
__device__ __forceinline__ void cp_wait2()  { asm volatile("cp.async.wait_group 2;"  ::: "memory"); }
__device__ __forceinline__ void cp_wait1()  { asm volatile("cp.async.wait_group 1;"  ::: "memory"); }
__device__ __forceinline__ void cp_wait0()  { asm volatile("cp.async.wait_group 0;"  ::: "memory"); }

__device__ __forceinline__ void ld4(uint32_t& r0, uint32_t& r1, uint32_t& r2, uint32_t& r3, uint32_t a) {
    asm volatile("ldmatrix.sync.aligned.m8n8.x4.shared.b16 {%0,%1,%2,%3}, [%4];"
                 : "=r"(r0), "=r"(r1), "=r"(r2), "=r"(r3) : "r"(a));
}
__device__ __forceinline__ void ld4t(uint32_t& r0, uint32_t& r1, uint32_t& r2, uint32_t& r3, uint32_t a) {
    asm volatile("ldmatrix.sync.aligned.m8n8.x4.trans.shared.b16 {%0,%1,%2,%3}, [%4];"
                 : "=r"(r0), "=r"(r1), "=r"(r2), "=r"(r3) : "r"(a));
}
// f16 MMA, f32 accumulate: m16n8k16
__device__ __forceinline__ void mma16(float& c0, float& c1, float& c2, float& c3,
                                      uint32_t a0, uint32_t a1, uint32_t a2, uint32_t a3,
                                      uint32_t b0, uint32_t b1) {
    asm volatile("mma.sync.aligned.m16n8k16.row.col.f32.f16.f16.f32 "
                 "{%0,%1,%2,%3}, {%4,%5,%6,%7}, {%8,%9}, {%0,%1,%2,%3};"
                 : "+f"(c0), "+f"(c1), "+f"(c2), "+f"(c3)
                 : "r"(a0), "r"(a1), "r"(a2), "r"(a3), "r"(b0), "r"(b1));
}

// ---------- packed f32x2 helpers ----------
__device__ __forceinline__ ull pack2(float x, float y) {
    ull r; asm("mov.b64 %0, {%1,%2};" : "=l"(r) : "f"(x), "f"(y)); return r;
}
__device__ __forceinline__ void unpack2(ull v, float &x, float &y) {
    asm("mov.b64 {%0,%1}, %2;" : "=f"(x), "=f"(y) : "l"(v));
}
__device__ __forceinline__ void ffma2(ull &c, ull a, ull b) {
    asm("fma.rn.f32x2 %0, %1, %2, %3;" : "=l"(c) : "l"(a), "l"(b), "l"(c));
}
__device__ __forceinline__ uint32_t h2u(__half2 h) { return *(uint32_t*)&h; }

// ---------- scratch (device globals: allocation-free) ----------
__device__ __align__(256) __half g_Uh[(size_t)NMOL * MA * NF * F];   // 134 MB
__device__ __align__(256) __half g_Th[(size_t)NMOL * MA * HID];      // 32 MB
__device__ __align__(256) __half g_hh[(size_t)NMOL * MA * F];        // 8 MB
__device__ __align__(256) __half g_W1h[(size_t)DIN * HID];           // 2.2 MB  (k-major, as W1)
__device__ __align__(256) __half g_W2h[(size_t)HID * F];             // 128 KB  (k-major, as W2)

// ---------- K0: copy z (as float) and r into the output buffer ----------
__global__ void k0_copy(const int* __restrict__ z, const float* __restrict__ r,
                        float* __restrict__ oz, float* __restrict__ orr,
                        int nz, int nr) {
    int i = blockIdx.x * blockDim.x + threadIdx.x;
    if (i < nz) oz[i]  = (float)z[i];
    if (i < nr) orr[i] = r[i];
}

// ---------- f32 -> f16 (RNE) convert ----------
__global__ void kcvt(const float* __restrict__ s, __half* __restrict__ d, int n) {
    int i = (blockIdx.x * blockDim.x + threadIdx.x) * 4;
    if (i < n) {
        float4 v = *(const float4*)(s + i);
        __half2 a = __floats2half2_rn(v.x, v.y);
        __half2 b = __floats2half2_rn(v.z, v.w);
        *(uint2*)(d + i) = make_uint2(h2u(a), h2u(b));
    }
}

// ---------- K1 fused: RBF weights + neighbor aggregation (FFMA2, half output) ----------
__global__ __launch_bounds__(256) void k1_fused(
    const int* __restrict__ z, const float* __restrict__ r,
    const float* __restrict__ dist, const float* __restrict__ widths,
    const float* __restrict__ h, __half* __restrict__ U)
{
    __shared__ float sh_h[MA * F];    // 32 KB
    __shared__ float sh_w[MA * MA];   // 16 KB (temp: r + mask, then w_f tiles)
    int n = blockIdx.x, tid = threadIdx.x;

    {
        const float4* hg = (const float4*)(h + (size_t)n * MA * F);
        float4* hs = (float4*)sh_h;
        for (int i = tid; i < MA * F / 4; i += 256) hs[i] = hg[i];
    }
    float* tr  = sh_w;         // 192 floats
    float* msk = sh_w + 192;   // 64 floats
    if (tid < 192) tr[tid] = r[(size_t)n * MA * 3 + tid];
    if (tid >= 192 && tid < 256) msk[tid - 192] = (z[n * MA + (tid - 192)] > -1) ? 1.0f : 0.0f;
    __syncthreads();

    float d[16];
#pragma unroll
    for (int q = 0; q < 16; q++) {
        int p = tid + q * 256;
        int a = p >> 6, b = p & 63;
        float dx = tr[a * 3 + 0] - tr[b * 3 + 0];
        float dy = tr[a * 3 + 1] - tr[b * 3 + 1];
        float dz = tr[a * 3 + 2] - tr[b * 3 + 2];
        float dd = sqrtf(dx * dx + dy * dy + dz * dz + 1e-12f);
        if (msk[a] * msk[b] == 0.0f) dd = 1e9f;
        d[q] = dd;
    }
    __syncthreads();

    int tm = tid >> 4, tn = tid & 15;
    int a0 = tm * 4, c0 = tn * 8;
    __half* Un = U + (size_t)n * MA * (NF * F);

    for (int f = 0; f < NF; f++) {
        float mu   = __ldg(&dist[f]);
        float isg2 = 1.4426950408889634f / __ldg(&widths[f]);   // fold log2(e)
#pragma unroll
        for (int q = 0; q < 16; q++) {
            float t = d[q] - mu;
            sh_w[tid + q * 256] = 5.0f * exp2f(-t * t * isg2);
        }
        __syncthreads();

        ull acc[4][4];
#pragma unroll
        for (int i = 0; i < 4; i++)
#pragma unroll
            for (int j = 0; j < 4; j++) acc[i][j] = 0ull;

#pragma unroll 4
        for (int b = 0; b < MA; b++) {
            float4 h0 = *(const float4*)&sh_h[b * F + c0];
            float4 h1 = *(const float4*)&sh_h[b * F + c0 + 4];
            ull hp[4] = { pack2(h0.x, h0.y), pack2(h0.z, h0.w),
                          pack2(h1.x, h1.y), pack2(h1.z, h1.w) };
#pragma unroll
            for (int i = 0; i < 4; i++) {
                float wv = sh_w[(a0 + i) * MA + b];
                ull wd = pack2(wv, wv);
#pragma unroll
                for (int j = 0; j < 4; j++) ffma2(acc[i][j], wd, hp[j]);
            }
        }
#pragma unroll
        for (int i = 0; i < 4; i++) {
            float o[8];
#pragma unroll
            for (int j = 0; j < 4; j++) unpack2(acc[i][j], o[2 * j], o[2 * j + 1]);
            uint4 pk;
            pk.x = h2u(__floats2half2_rn(o[0], o[1]));
            pk.y = h2u(__floats2half2_rn(o[2], o[3]));
            pk.z = h2u(__floats2half2_rn(o[4], o[5]));
            pk.w = h2u(__floats2half2_rn(o[6], o[7]));
            *(uint4*)&Un[(size_t)(a0 + i) * (NF * F) + f * F + c0] = pk;
        }
        __syncthreads();
    }
}

// ======================= K2: T = silu([h|U] @ W1 + b1) via f16 mma =======================
// BM=128, BN=256, BK=64 halves, 4-stage cp.async. 8 warps 2(m)x4(n), warp tile 64x64.
// A smem: [128 rows][64 halves=128B] swizzled; B smem: [64 k-rows][256 halves=512B] swizzled.
#define K2_CHUNKS 34
#define K2_A_BYTES 16384
#define K2_B_BYTES 32768
#define K2_STAGE   (K2_A_BYTES + K2_B_BYTES)   // 49152
#define K2_DYN     (4 * K2_STAGE)              // 196608

__device__ __forceinline__ void k2_load(int j, int row0, int col0,
    const __half* __restrict__ hh, const __half* __restrict__ Uh,
    const __half* __restrict__ W1h, uint32_t sA, uint32_t sB, int tid)
{
    int k0 = j * 64;
    const __half* Ab; size_t lda;
    if (k0 < F) { Ab = hh + (size_t)row0 * F + k0;         lda = F; }
    else        { Ab = Uh + (size_t)row0 * 2048 + (k0 - F); lda = 2048; }
#pragma unroll
    for (int p = 0; p < 4; p++) {
        int idx = p * 256 + tid;
        int m = idx >> 3, u = idx & 7;
        cpasync16(sA + m * 128 + (((u ^ (m & 7))) << 4), Ab + (size_t)m * lda + u * 8);
    }
    const __half* Bb = W1h + (size_t)k0 * HID + col0;
#pragma unroll
    for (int p = 0; p < 8; p++) {
        int idx = p * 256 + tid;
        int kr = idx >> 5, u = idx & 31;
        cpasync16(sB + kr * 512 + (((u ^ (kr & 7))) << 4), Bb + (size_t)kr * HID + u * 8);
    }
}

__global__ __launch_bounds__(256, 1) void k2_tc(
    const __half* __restrict__ hh, const __half* __restrict__ Uh,
    const __half* __restrict__ W1h, const float* __restrict__ b1,
    __half* __restrict__ T)
{
    extern __shared__ char dynsm[];
    uint32_t dbase = smem_to_u32(dynsm);
    int tid = threadIdx.x, wid = tid >> 5, lane = tid & 31;
    int gid = lane >> 2, tig = lane & 3;
    int warp_m = wid >> 2, warp_n = wid & 3;
    int col0 = blockIdx.x * 256, row0 = blockIdx.y * 128;

    float acc[4][8][4];
#pragma unroll
    for (int mf = 0; mf < 4; mf++)
#pragma unroll
        for (int nf = 0; nf < 8; nf++)
#pragma unroll
            for (int q = 0; q < 4; q++) acc[mf][nf][q] = 0.0f;

    // ldmatrix address components
    int aRow = warp_m * 64 + (lane & 15);               // + mf*16
    int aSw  = lane & 7;
    int kuHi = (lane >> 4);                             // 0/1
    int bKrl = (lane & 7) + ((lane >> 3) & 1) * 8;      // 0..15 within k16
    int bNuL = (lane >> 4);                             // 0/1

    // prologue: 3 stages
#pragma unroll
    for (int s = 0; s < 3; s++) {
        k2_load(s, row0, col0, hh, Uh, W1h, dbase + s * K2_STAGE, dbase + s * K2_STAGE + K2_A_BYTES, tid);
        cp_commit();
    }

    for (int j = 0; j < K2_CHUNKS; j++) {
        int s = j & 3;
        if (j <= K2_CHUNKS - 3)      cp_wait2();
        else if (j == K2_CHUNKS - 2) cp_wait1();
        else                         cp_wait0();
        __syncthreads();
        if (j + 3 < K2_CHUNKS) {
            int s2 = (j + 3) & 3;
            k2_load(j + 3, row0, col0, hh, Uh, W1h,
                    dbase + s2 * K2_STAGE, dbase + s2 * K2_STAGE + K2_A_BYTES, tid);
            cp_commit();
        }
        uint32_t sA = dbase + s * K2_STAGE;
        uint32_t sB = sA + K2_A_BYTES;
#pragma unroll
        for (int kk = 0; kk < 4; kk++) {
            uint32_t a[4][4];
#pragma unroll
            for (int mf = 0; mf < 4; mf++) {
                int rowm = aRow + mf * 16;
                uint32_t ad = sA + rowm * 128 + (((kk * 2 + kuHi) ^ aSw) << 4);
                ld4(a[mf][0], a[mf][1], a[mf][2], a[mf][3], ad);
            }
#pragma unroll
            for (int np = 0; np < 4; np++) {
                int krow = kk * 16 + bKrl;
                int nu = warp_n * 8 + np * 2 + bNuL;
                uint32_t bd = sB + krow * 512 + (((nu ^ (krow & 7))) << 4);
                uint32_t b0, b1r, b2, b3;
                ld4t(b0, b1r, b2, b3, bd);
                int nf0 = np * 2, nf1 = nf0 + 1;
#pragma unroll
                for (int mf = 0; mf < 4; mf++) {
                    mma16(acc[mf][nf0][0], acc[mf][nf0][1], acc[mf][nf0][2], acc[mf][nf0][3],
                          a[mf][0], a[mf][1], a[mf][2], a[mf][3], b0, b1r);
                    mma16(acc[mf][nf1][0], acc[mf][nf1][1], acc[mf][nf1][2], acc[mf][nf1][3],
                          a[mf][0], a[mf][1], a[mf][2], a[mf][3], b2, b3);
                }
            }
        }
    }
    __syncthreads();

    // epilogue: bias + silu -> T (half)
#pragma unroll
    for (int mf = 0; mf < 4; mf++) {
        int rr = row0 + warp_m * 64 + mf * 16 + gid;
#pragma unroll
        for (int nf = 0; nf < 8; nf++) {
            int cc = col0 + warp_n * 64 + nf * 8 + tig * 2;
            float ba = __ldg(&b1[cc]), bb = __ldg(&b1[cc + 1]);
            float x0 = acc[mf][nf][0] + ba, x1 = acc[mf][nf][1] + bb;
            float x2 = acc[mf][nf][2] + ba, x3 = acc[mf][nf][3] + bb;
            x0 = x0 / (1.0f + __expf(-x0));
            x1 = x1 / (1.0f + __expf(-x1));
            x2 = x2 / (1.0f + __expf(-x2));
            x3 = x3 / (1.0f + __expf(-x3));
            *(uint32_t*)&T[(size_t)rr * HID + cc]       = h2u(__floats2half2_rn(x0, x1));
            *(uint32_t*)&T[(size_t)(rr + 8) * HID + cc] = h2u(__floats2half2_rn(x2, x3));
        }
    }
}

// ======================= K3: out = h + 0.1*(T @ W2 + b2)*mask via f16 mma =======================
// BM=128, BN=128, BK=64, 3-stage. 8 warps 2(m)x4(n), warp tile 64x32.
#define K3_CHUNKS 8
#define K3_A_BYTES 16384
#define K3_B_BYTES 16384
#define K3_STAGE   (K3_A_BYTES + K3_B_BYTES)   // 32768
#define K3_DYN     (3 * K3_STAGE)              // 98304

__device__ __forceinline__ void k3_load(int j, int row0,
    const __half* __restrict__ T, const __half* __restrict__ W2h,
    uint32_t sA, uint32_t sB, int tid)
{
    int k0 = j * 64;
    const __half* Ab = T + (size_t)row0 * HID + k0;
#pragma unroll
    for (int p = 0; p < 4; p++) {
        int idx = p * 256 + tid;
        int m = idx >> 3, u = idx & 7;
        cpasync16(sA + m * 128 + (((u ^ (m & 7))) << 4), Ab + (size_t)m * HID + u * 8);
    }
    const __half* Bb = W2h + (size_t)k0 * F;
#pragma unroll
    for (int p = 0; p < 4; p++) {
        int idx = p * 256 + tid;
        int kr = idx >> 4, u = idx & 15;
        cpasync16(sB + kr * 256 + (((u ^ (kr & 7))) << 4), Bb + (size_t)kr * F + u * 8);
    }
}

__global__ __launch_bounds__(256, 1) void k3_tc(
    const __half* __restrict__ T, const __half* __restrict__ W2h,
    const float* __restrict__ b2, const float* __restrict__ h,
    const int* __restrict__ z, float* __restrict__ out)
{
    extern __shared__ char dynsm[];
    uint32_t dbase = smem_to_u32(dynsm);
    int tid = threadIdx.x, wid = tid >> 5, lane = tid & 31;
    int gid = lane >> 2, tig = lane & 3;
    int warp_m = wid >> 2, warp_n = wid & 3;
    int row0 = blockIdx.x * 128;

    float acc[4][4][4];
#pragma unroll
    for (int mf = 0; mf < 4; mf++)
#pragma unroll
        for (int nf = 0; nf < 4; nf++)
#pragma unroll
            for (int q = 0; q < 4; q++) acc[mf][nf][q] = 0.0f;

    int aRow = warp_m * 64 + (lane & 15);
    int aSw  = lane & 7;
    int kuHi = (lane >> 4);
    int bKrl = (lane & 7) + ((lane >> 3) & 1) * 8;
    int bNuL = (lane >> 4);

    k3_load(0, row0, T, W2h, dbase, dbase + K3_A_BYTES, tid);
    cp_commit();
    k3_load(1, row0, T, W2h, dbase + K3_STAGE, dbase + K3_STAGE + K3_A_BYTES, tid);
    cp_commit();

    for (int j = 0; j < K3_CHUNKS; j++) {
        int s = j % 3;
        if (j < K3_CHUNKS - 1) cp_wait1(); else cp_wait0();
        __syncthreads();
        if (j + 2 < K3_CHUNKS) {
            int s2 = (j + 2) % 3;
            k3_load(j + 2, row0, T, W2h,
                    dbase + s2 * K3_STAGE, dbase + s2 * K3_STAGE + K3_A_BYTES, tid);
            cp_commit();
        }
        uint32_t sA = dbase + s * K3_STAGE;
        uint32_t sB = sA + K3_A_BYTES;
#pragma unroll
        for (int kk = 0; kk < 4; kk++) {
            uint32_t a[4][4];
#pragma unroll
            for (int mf = 0; mf < 4; mf++) {
                int rowm = aRow + mf * 16;
                uint32_t ad = sA + rowm * 128 + (((kk * 2 + kuHi) ^ aSw) << 4);
                ld4(a[mf][0], a[mf][1], a[mf][2], a[mf][3], ad);
            }
#pragma unroll
            for (int np = 0; np < 2; np++) {
                int krow = kk * 16 + bKrl;
                int nu = warp_n * 4 + np * 2 + bNuL;
                uint32_t bd = sB + krow * 256 + (((nu ^ (krow & 7))) << 4);
                uint32_t b0, b1r, b2, b3;
                ld4t(b0, b1r, b2, b3, bd);
                int nf0 = np * 2, nf1 = nf0 + 1;
#pragma unroll
                for (int mf = 0; mf < 4; mf++) {
                    mma16(acc[mf][nf0][0], acc[mf][nf0][1], acc[mf][nf0][2], acc[mf][nf0][3],
                          a[mf][0], a[mf][1], a[mf][2], a[mf][3], b0, b1r);
                    mma16(acc[mf][nf1][0], acc[mf][nf1][1], acc[mf][nf1][2], acc[mf][nf1][3],
                          a[mf][0], a[mf][1], a[mf][2], a[mf][3], b2, b3);
                }
            }
        }
        __syncthreads();
    }

    // epilogue: residual + mask (fp32 out)
#pragma unroll
    for (int mf = 0; mf < 4; mf++) {
        int rr = row0 + warp_m * 64 + mf * 16 + gid;
        float m0 = (__ldg(&z[rr])     > -1) ? 0.1f : 0.0f;
        float m8 = (__ldg(&z[rr + 8]) > -1) ? 0.1f : 0.0f;
#pragma unroll
        for (int nf = 0; nf < 4; nf++) {
            int cc = warp_n * 32 + nf * 8 + tig * 2;
            float ba = __ldg(&b2[cc]), bb = __ldg(&b2[cc + 1]);
            float2 h0 = *(const float2*)&h[(size_t)rr * F + cc];
            float2 h8 = *(const float2*)&h[(size_t)(rr + 8) * F + cc];
            float o0 = h0.x + m0 * (acc[mf][nf][0] + ba);
            float o1 = h0.y + m0 * (acc[mf][nf][1] + bb);
            float o2 = h8.x + m8 * (acc[mf][nf][2] + ba);
            float o3 = h8.y + m8 * (acc[mf][nf][3] + bb);
            *(float2*)&out[(size_t)rr * F + cc]       = make_float2(o0, o1);
            *(float2*)&out[(size_t)(rr + 8) * F + cc] = make_float2(o2, o3);
        }
    }
}

extern "C" void kernel_launch(void* const* d_in, const int* in_sizes, int n_in,
                              void* d_out, int out_size)
{
    const int*   z    = (const int*)d_in[0];
    const float* r    = (const float*)d_in[1];
    const float* h    = (const float*)d_in[2];
    const float* dist = (const float*)d_in[3];
    const float* wids = (const float*)d_in[4];
    const float* W1   = (const float*)d_in[5];
    const float* b1   = (const float*)d_in[6];
    const float* W2   = (const float*)d_in[7];
    const float* b2   = (const float*)d_in[8];

    __half *Uh, *Th, *hh, *W1h, *W2h;
    cudaGetSymbolAddress((void**)&Uh,  g_Uh);
    cudaGetSymbolAddress((void**)&Th,  g_Th);
    cudaGetSymbolAddress((void**)&hh,  g_hh);
    cudaGetSymbolAddress((void**)&W1h, g_W1h);
    cudaGetSymbolAddress((void**)&W2h, g_W2h);

    int nz = in_sizes[0], nr = in_sizes[1], nh = in_sizes[2];
    int nmol = nh / (MA * F);            // 512
    int rows = nmol * MA;                // 32768

    float* out   = (float*)d_out;
    float* out_h = out;
    if (out_size == nz + nr + nh) {
        k0_copy<<<(nr + 255) / 256, 256>>>(z, r, out, out + nz, nz, nr);
        out_h = out + nz + nr;
    }

    // f32 -> f16 converts (RNE)
    kcvt<<<(nh / 4 + 255) / 256, 256>>>(h, hh, nh);
    kcvt<<<(DIN * HID / 4 + 255) / 256, 256>>>(W1, W1h, DIN * HID);
    kcvt<<<(HID * F / 4 + 255) / 256, 256>>>(W2, W2h, HID * F);

    k1_fused<<<nmol, 256>>>(z, r, dist, wids, h, Uh);

    cudaFuncSetAttribute(k2_tc, cudaFuncAttributeMaxDynamicSharedMemorySize, K2_DYN);
    k2_tc<<<dim3(HID / 256, rows / 128), 256, K2_DYN>>>(hh, Uh, W1h, b1, Th);

    cudaFuncSetAttribute(k3_tc, cudaFuncAttributeMaxDynamicSharedMemorySize, K3_DYN);
    k3_tc<<<rows / 128, 256, K3_DYN>>>(Th, W2h, b2, h, z, out_h);
}

// round 9
// speedup vs baseline: 6.2557x; 1.7122x over previous
#include <cuda_runtime.h>
#include <cuda_fp16.h>
#include <cstdint>

typedef unsigned long long ull;

#define NMOL 512
#define MA   64
#define F    128
#define NF   16
#define DIN  2176   // F*(1+NF)
#define HID  512

// ======================= helpers =======================
__device__ __forceinline__ uint32_t smem_to_u32(const void* p) {
    uint32_t a;
    asm("{ .reg .u64 t; cvta.to.shared.u64 t, %1; cvt.u32.u64 %0, t; }" : "=r"(a) : "l"(p));
    return a;
}
__device__ __forceinline__ void cpasync16(uint32_t s, const void* g) {
    asm volatile("cp.async.cg.shared.global [%0], [%1], 16;" :: "r"(s), "l"(g) : "memory");
}
__device__ __forceinline__ void cp_commit() { asm volatile("cp.async.commit_group;" ::: "memory"); }
__device__ __forceinline__ void cp_wait2()  { asm volatile("cp.async.wait_group 2;"  ::: "memory"); }
__device__ __forceinline__ void cp_wait1()  { asm volatile("cp.async.wait_group 1;"  ::: "memory"); }
__device__ __forceinline__ void cp_wait0()  { asm volatile("cp.async.wait_group 0;"  ::: "memory"); }

__device__ __forceinline__ void ld4(uint32_t& r0, uint32_t& r1, uint32_t& r2, uint32_t& r3, uint32_t a) {
    asm volatile("ldmatrix.sync.aligned.m8n8.x4.shared.b16 {%0,%1,%2,%3}, [%4];"
                 : "=r"(r0), "=r"(r1), "=r"(r2), "=r"(r3) : "r"(a));
}
__device__ __forceinline__ void ld4t(uint32_t& r0, uint32_t& r1, uint32_t& r2, uint32_t& r3, uint32_t a) {
    asm volatile("ldmatrix.sync.aligned.m8n8.x4.trans.shared.b16 {%0,%1,%2,%3}, [%4];"
                 : "=r"(r0), "=r"(r1), "=r"(r2), "=r"(r3) : "r"(a));
}
// f16 MMA, f32 accumulate: m16n8k16
__device__ __forceinline__ void mma16(float& c0, float& c1, float& c2, float& c3,
                                      uint32_t a0, uint32_t a1, uint32_t a2, uint32_t a3,
                                      uint32_t b0, uint32_t b1) {
    asm volatile("mma.sync.aligned.m16n8k16.row.col.f32.f16.f16.f32 "
                 "{%0,%1,%2,%3}, {%4,%5,%6,%7}, {%8,%9}, {%0,%1,%2,%3};"
                 : "+f"(c0), "+f"(c1), "+f"(c2), "+f"(c3)
                 : "r"(a0), "r"(a1), "r"(a2), "r"(a3), "r"(b0), "r"(b1));
}
__device__ __forceinline__ uint32_t h2u(__half2 h) { return *(uint32_t*)&h; }

// ---------- scratch (device globals: allocation-free) ----------
__device__ __align__(256) __half g_Uh[(size_t)NMOL * MA * NF * F];   // 134 MB
__device__ __align__(256) __half g_Th[(size_t)NMOL * MA * HID];      // 32 MB
__device__ __align__(256) __half g_hh[(size_t)NMOL * MA * F];        // 8 MB
__device__ __align__(256) __half g_W1h[(size_t)DIN * HID];           // 2.2 MB  (k-major, as W1)
__device__ __align__(256) __half g_W2h[(size_t)HID * F];             // 128 KB  (k-major, as W2)

// ---------- K0: copy z (as float) and r into the output buffer ----------
__global__ void k0_copy(const int* __restrict__ z, const float* __restrict__ r,
                        float* __restrict__ oz, float* __restrict__ orr,
                        int nz, int nr) {
    int i = blockIdx.x * blockDim.x + threadIdx.x;
    if (i < nz) oz[i]  = (float)z[i];
    if (i < nr) orr[i] = r[i];
}

// ---------- f32 -> f16 (RNE) convert: h, W1, W2 in one launch ----------
__global__ void kcvt_all(const float* __restrict__ h,  const float* __restrict__ W1,
                         const float* __restrict__ W2, __half* __restrict__ hh,
                         __half* __restrict__ W1h, __half* __restrict__ W2h, int nh)
{
    const int n1 = DIN * HID, n2 = HID * F;
    int i = (blockIdx.x * blockDim.x + threadIdx.x) * 4;
    const float* s; __half* d; int off;
    if (i < nh)                { s = h;  d = hh;  off = 0; }
    else if (i < nh + n1)      { s = W1; d = W1h; off = nh; }
    else if (i < nh + n1 + n2) { s = W2; d = W2h; off = nh + n1; }
    else return;
    int j = i - off;
    float4 v = *(const float4*)(s + j);
    __half2 a = __floats2half2_rn(v.x, v.y);
    __half2 b = __floats2half2_rn(v.z, v.w);
    *(uint2*)(d + j) = make_uint2(h2u(a), h2u(b));
}

// ======================= K1: RBF + aggregation on tensor cores =======================
// Per molecule (CTA, 256 thr = 8 warps as 4(m) x 2(n)):
//   for f in 0..15:  U[a, f*128+c] = sum_b w_f[a,b] * h[b,c]   (f16 mma, f32 accum)
// A = w_f (64x64 f16, computed in-kernel, swizzled 128B rows), B = h (64x128 f16, k-major 256B rows).
__global__ __launch_bounds__(256) void k1_tc(
    const int* __restrict__ z, const float* __restrict__ r,
    const float* __restrict__ dist, const float* __restrict__ widths,
    const __half* __restrict__ hh, __half* __restrict__ U)
{
    __shared__ __half sh_h[MA * F];   // 16 KB, swizzled k-major (256B rows)
    __shared__ __half sh_w[MA * MA];  // 8 KB, swizzled row-major (128B rows)
    __shared__ float s_r[192];
    __shared__ float s_m[64];
    int n = blockIdx.x, tid = threadIdx.x;
    int wid = tid >> 5, lane = tid & 31;
    int gid = lane >> 2, tig = lane & 3;
    int warp_m = wid >> 1, warp_n = wid & 1;
    uint32_t hbase = smem_to_u32(sh_h), wbase = smem_to_u32(sh_w);

    // async-load h tile (64 rows x 256B), swizzled for ld4t
    {
        const __half* hg = hh + (size_t)n * MA * F;
#pragma unroll
        for (int p = 0; p < 4; p++) {
            int idx = p * 256 + tid;
            int row = idx >> 4, u = idx & 15;
            cpasync16(hbase + row * 256 + ((u ^ (row & 7)) << 4), hg + (size_t)row * F + u * 8);
        }
        cp_commit();
    }
    if (tid < 192) s_r[tid] = r[(size_t)n * 192 + tid];
    if (tid >= 192) s_m[tid - 192] = (z[n * MA + (tid - 192)] > -1) ? 1.0f : 0.0f;
    __syncthreads();

    // distances: thread owns b = tid&63, rows a = (tid>>6) + 4q
    float d[16];
    {
        int b = tid & 63;
        float bx = s_r[b * 3 + 0], by = s_r[b * 3 + 1], bz = s_r[b * 3 + 2];
        float mb = s_m[b];
#pragma unroll
        for (int q = 0; q < 16; q++) {
            int a = (tid >> 6) + 4 * q;
            float dx = s_r[a * 3 + 0] - bx;
            float dy = s_r[a * 3 + 1] - by;
            float dz = s_r[a * 3 + 2] - bz;
            float dd = sqrtf(dx * dx + dy * dy + dz * dz + 1e-12f);
            if (s_m[a] * mb == 0.0f) dd = 1e9f;
            d[q] = dd;
        }
    }

    // ldmatrix address components (same scheme as k2/k3)
    int aRow = warp_m * 16 + (lane & 15);
    int aSw  = lane & 7;
    int kuHi = (lane >> 4);
    int bKrl = (lane & 7) + ((lane >> 3) & 1) * 8;
    int bNuL = (lane >> 4);
    int wb   = tid & 63;                              // b column this thread writes
    __half* Un = U + (size_t)n * MA * (NF * F);

    for (int f = 0; f < NF; f++) {
        float mu   = __ldg(&dist[f]);
        float isg2 = 1.4426950408889634f / __ldg(&widths[f]);
        __syncthreads();   // previous mma done reading sh_w
        // compute + store w_f as f16 into swizzled A layout (generic pointer store!)
#pragma unroll
        for (int q = 0; q < 16; q++) {
            int a = (tid >> 6) + 4 * q;
            float t = d[q] - mu;
            __half wv = __float2half_rn(5.0f * exp2f(-t * t * isg2));
            int off = a * 128 + ((((wb >> 3) ^ (a & 7))) << 4) + (wb & 7) * 2;
            *(__half*)((char*)sh_w + off) = wv;
        }
        if (f == 0) cp_wait0();
        __syncthreads();

        float acc[8][4];
#pragma unroll
        for (int nf = 0; nf < 8; nf++)
#pragma unroll
            for (int q = 0; q < 4; q++) acc[nf][q] = 0.0f;

#pragma unroll
        for (int kk = 0; kk < 4; kk++) {
            uint32_t a0, a1, a2, a3;
            uint32_t ad = wbase + aRow * 128 + (((kk * 2 + kuHi) ^ aSw) << 4);
            ld4(a0, a1, a2, a3, ad);
#pragma unroll
            for (int np = 0; np < 4; np++) {
                int krow = kk * 16 + bKrl;
                int nu = warp_n * 8 + np * 2 + bNuL;
                uint32_t bd = hbase + krow * 256 + ((nu ^ (krow & 7)) << 4);
                uint32_t b0, b1r, b2, b3;
                ld4t(b0, b1r, b2, b3, bd);
                int nf0 = np * 2, nf1 = nf0 + 1;
                mma16(acc[nf0][0], acc[nf0][1], acc[nf0][2], acc[nf0][3],
                      a0, a1, a2, a3, b0, b1r);
                mma16(acc[nf1][0], acc[nf1][1], acc[nf1][2], acc[nf1][3],
                      a0, a1, a2, a3, b2, b3);
            }
        }
        // write U tile for this f (f16)
        int rr = warp_m * 16 + gid;
#pragma unroll
        for (int nf = 0; nf < 8; nf++) {
            int cc = warp_n * 64 + nf * 8 + tig * 2;
            *(uint32_t*)&Un[(size_t)rr * (NF * F) + f * F + cc] =
                h2u(__floats2half2_rn(acc[nf][0], acc[nf][1]));
            *(uint32_t*)&Un[(size_t)(rr + 8) * (NF * F) + f * F + cc] =
                h2u(__floats2half2_rn(acc[nf][2], acc[nf][3]));
        }
    }
}

// ======================= K2: T = silu([h|U] @ W1 + b1) via f16 mma =======================
// BM=128, BN=256, BK=64 halves, 4-stage cp.async. 8 warps 2(m)x4(n), warp tile 64x64.
#define K2_CHUNKS 34
#define K2_A_BYTES 16384
#define K2_B_BYTES 32768
#define K2_STAGE   (K2_A_BYTES + K2_B_BYTES)   // 49152
#define K2_DYN     (4 * K2_STAGE)              // 196608

__device__ __forceinline__ void k2_load(int j, int row0, int col0,
    const __half* __restrict__ hh, const __half* __restrict__ Uh,
    const __half* __restrict__ W1h, uint32_t sA, uint32_t sB, int tid)
{
    int k0 = j * 64;
    const __half* Ab; size_t lda;
    if (k0 < F) { Ab = hh + (size_t)row0 * F + k0;          lda = F; }
    else        { Ab = Uh + (size_t)row0 * 2048 + (k0 - F); lda = 2048; }
#pragma unroll
    for (int p = 0; p < 4; p++) {
        int idx = p * 256 + tid;
        int m = idx >> 3, u = idx & 7;
        cpasync16(sA + m * 128 + (((u ^ (m & 7))) << 4), Ab + (size_t)m * lda + u * 8);
    }
    const __half* Bb = W1h + (size_t)k0 * HID + col0;
#pragma unroll
    for (int p = 0; p < 8; p++) {
        int idx = p * 256 + tid;
        int kr = idx >> 5, u = idx & 31;
        cpasync16(sB + kr * 512 + (((u ^ (kr & 7))) << 4), Bb + (size_t)kr * HID + u * 8);
    }
}

__global__ __launch_bounds__(256, 1) void k2_tc(
    const __half* __restrict__ hh, const __half* __restrict__ Uh,
    const __half* __restrict__ W1h, const float* __restrict__ b1,
    __half* __restrict__ T)
{
    extern __shared__ char dynsm[];
    uint32_t dbase = smem_to_u32(dynsm);
    int tid = threadIdx.x, wid = tid >> 5, lane = tid & 31;
    int gid = lane >> 2, tig = lane & 3;
    int warp_m = wid >> 2, warp_n = wid & 3;
    int col0 = blockIdx.x * 256, row0 = blockIdx.y * 128;

    float acc[4][8][4];
#pragma unroll
    for (int mf = 0; mf < 4; mf++)
#pragma unroll
        for (int nf = 0; nf < 8; nf++)
#pragma unroll
            for (int q = 0; q < 4; q++) acc[mf][nf][q] = 0.0f;

    int aRow = warp_m * 64 + (lane & 15);
    int aSw  = lane & 7;
    int kuHi = (lane >> 4);
    int bKrl = (lane & 7) + ((lane >> 3) & 1) * 8;
    int bNuL = (lane >> 4);

#pragma unroll
    for (int s = 0; s < 3; s++) {
        k2_load(s, row0, col0, hh, Uh, W1h, dbase + s * K2_STAGE, dbase + s * K2_STAGE + K2_A_BYTES, tid);
        cp_commit();
    }

    for (int j = 0; j < K2_CHUNKS; j++) {
        int s = j & 3;
        if (j <= K2_CHUNKS - 3)      cp_wait2();
        else if (j == K2_CHUNKS - 2) cp_wait1();
        else                         cp_wait0();
        __syncthreads();
        if (j + 3 < K2_CHUNKS) {
            int s2 = (j + 3) & 3;
            k2_load(j + 3, row0, col0, hh, Uh, W1h,
                    dbase + s2 * K2_STAGE, dbase + s2 * K2_STAGE + K2_A_BYTES, tid);
            cp_commit();
        }
        uint32_t sA = dbase + s * K2_STAGE;
        uint32_t sB = sA + K2_A_BYTES;
#pragma unroll
        for (int kk = 0; kk < 4; kk++) {
            uint32_t a[4][4];
#pragma unroll
            for (int mf = 0; mf < 4; mf++) {
                int rowm = aRow + mf * 16;
                uint32_t ad = sA + rowm * 128 + (((kk * 2 + kuHi) ^ aSw) << 4);
                ld4(a[mf][0], a[mf][1], a[mf][2], a[mf][3], ad);
            }
#pragma unroll
            for (int np = 0; np < 4; np++) {
                int krow = kk * 16 + bKrl;
                int nu = warp_n * 8 + np * 2 + bNuL;
                uint32_t bd = sB + krow * 512 + (((nu ^ (krow & 7))) << 4);
                uint32_t b0, b1r, b2, b3;
                ld4t(b0, b1r, b2, b3, bd);
                int nf0 = np * 2, nf1 = nf0 + 1;
#pragma unroll
                for (int mf = 0; mf < 4; mf++) {
                    mma16(acc[mf][nf0][0], acc[mf][nf0][1], acc[mf][nf0][2], acc[mf][nf0][3],
                          a[mf][0], a[mf][1], a[mf][2], a[mf][3], b0, b1r);
                    mma16(acc[mf][nf1][0], acc[mf][nf1][1], acc[mf][nf1][2], acc[mf][nf1][3],
                          a[mf][0], a[mf][1], a[mf][2], a[mf][3], b2, b3);
                }
            }
        }
    }
    __syncthreads();

#pragma unroll
    for (int mf = 0; mf < 4; mf++) {
        int rr = row0 + warp_m * 64 + mf * 16 + gid;
#pragma unroll
        for (int nf = 0; nf < 8; nf++) {
            int cc = col0 + warp_n * 64 + nf * 8 + tig * 2;
            float ba = __ldg(&b1[cc]), bb = __ldg(&b1[cc + 1]);
            float x0 = acc[mf][nf][0] + ba, x1 = acc[mf][nf][1] + bb;
            float x2 = acc[mf][nf][2] + ba, x3 = acc[mf][nf][3] + bb;
            x0 = x0 / (1.0f + __expf(-x0));
            x1 = x1 / (1.0f + __expf(-x1));
            x2 = x2 / (1.0f + __expf(-x2));
            x3 = x3 / (1.0f + __expf(-x3));
            *(uint32_t*)&T[(size_t)rr * HID + cc]       = h2u(__floats2half2_rn(x0, x1));
            *(uint32_t*)&T[(size_t)(rr + 8) * HID + cc] = h2u(__floats2half2_rn(x2, x3));
        }
    }
}

// ======================= K3: out = h + 0.1*(T @ W2 + b2)*mask via f16 mma =======================
#define K3_CHUNKS 8
#define K3_A_BYTES 16384
#define K3_B_BYTES 16384
#define K3_STAGE   (K3_A_BYTES + K3_B_BYTES)
#define K3_DYN     (3 * K3_STAGE)

__device__ __forceinline__ void k3_load(int j, int row0,
    const __half* __restrict__ T, const __half* __restrict__ W2h,
    uint32_t sA, uint32_t sB, int tid)
{
    int k0 = j * 64;
    const __half* Ab = T + (size_t)row0 * HID + k0;
#pragma unroll
    for (int p = 0; p < 4; p++) {
        int idx = p * 256 + tid;
        int m = idx >> 3, u = idx & 7;
        cpasync16(sA + m * 128 + (((u ^ (m & 7))) << 4), Ab + (size_t)m * HID + u * 8);
    }
    const __half* Bb = W2h + (size_t)k0 * F;
#pragma unroll
    for (int p = 0; p < 4; p++) {
        int idx = p * 256 + tid;
        int kr = idx >> 4, u = idx & 15;
        cpasync16(sB + kr * 256 + (((u ^ (kr & 7))) << 4), Bb + (size_t)kr * F + u * 8);
    }
}

__global__ __launch_bounds__(256, 1) void k3_tc(
    const __half* __restrict__ T, const __half* __restrict__ W2h,
    const float* __restrict__ b2, const float* __restrict__ h,
    const int* __restrict__ z, float* __restrict__ out)
{
    extern __shared__ char dynsm[];
    uint32_t dbase = smem_to_u32(dynsm);
    int tid = threadIdx.x, wid = tid >> 5, lane = tid & 31;
    int gid = lane >> 2, tig = lane & 3;
    int warp_m = wid >> 2, warp_n = wid & 3;
    int row0 = blockIdx.x * 128;

    float acc[4][4][4];
#pragma unroll
    for (int mf = 0; mf < 4; mf++)
#pragma unroll
        for (int nf = 0; nf < 4; nf++)
#pragma unroll
            for (int q = 0; q < 4; q++) acc[mf][nf][q] = 0.0f;

    int aRow = warp_m * 64 + (lane & 15);
    int aSw  = lane & 7;
    int kuHi = (lane >> 4);
    int bKrl = (lane & 7) + ((lane >> 3) & 1) * 8;
    int bNuL = (lane >> 4);

    k3_load(0, row0, T, W2h, dbase, dbase + K3_A_BYTES, tid);
    cp_commit();
    k3_load(1, row0, T, W2h, dbase + K3_STAGE, dbase + K3_STAGE + K3_A_BYTES, tid);
    cp_commit();

    for (int j = 0; j < K3_CHUNKS; j++) {
        int s = j % 3;
        if (j < K3_CHUNKS - 1) cp_wait1(); else cp_wait0();
        __syncthreads();
        if (j + 2 < K3_CHUNKS) {
            int s2 = (j + 2) % 3;
            k3_load(j + 2, row0, T, W2h,
                    dbase + s2 * K3_STAGE, dbase + s2 * K3_STAGE + K3_A_BYTES, tid);
            cp_commit();
        }
        uint32_t sA = dbase + s * K3_STAGE;
        uint32_t sB = sA + K3_A_BYTES;
#pragma unroll
        for (int kk = 0; kk < 4; kk++) {
            uint32_t a[4][4];
#pragma unroll
            for (int mf = 0; mf < 4; mf++) {
                int rowm = aRow + mf * 16;
                uint32_t ad = sA + rowm * 128 + (((kk * 2 + kuHi) ^ aSw) << 4);
                ld4(a[mf][0], a[mf][1], a[mf][2], a[mf][3], ad);
            }
#pragma unroll
            for (int np = 0; np < 2; np++) {
                int krow = kk * 16 + bKrl;
                int nu = warp_n * 4 + np * 2 + bNuL;
                uint32_t bd = sB + krow * 256 + (((nu ^ (krow & 7))) << 4);
                uint32_t b0, b1r, b2, b3;
                ld4t(b0, b1r, b2, b3, bd);
                int nf0 = np * 2, nf1 = nf0 + 1;
#pragma unroll
                for (int mf = 0; mf < 4; mf++) {
                    mma16(acc[mf][nf0][0], acc[mf][nf0][1], acc[mf][nf0][2], acc[mf][nf0][3],
                          a[mf][0], a[mf][1], a[mf][2], a[mf][3], b0, b1r);
                    mma16(acc[mf][nf1][0], acc[mf][nf1][1], acc[mf][nf1][2], acc[mf][nf1][3],
                          a[mf][0], a[mf][1], a[mf][2], a[mf][3], b2, b3);
                }
            }
        }
        __syncthreads();
    }

#pragma unroll
    for (int mf = 0; mf < 4; mf++) {
        int rr = row0 + warp_m * 64 + mf * 16 + gid;
        float m0 = (__ldg(&z[rr])     > -1) ? 0.1f : 0.0f;
        float m8 = (__ldg(&z[rr + 8]) > -1) ? 0.1f : 0.0f;
#pragma unroll
        for (int nf = 0; nf < 4; nf++) {
            int cc = warp_n * 32 + nf * 8 + tig * 2;
            float ba = __ldg(&b2[cc]), bb = __ldg(&b2[cc + 1]);
            float2 h0 = *(const float2*)&h[(size_t)rr * F + cc];
            float2 h8 = *(const float2*)&h[(size_t)(rr + 8) * F + cc];
            float o0 = h0.x + m0 * (acc[mf][nf][0] + ba);
            float o1 = h0.y + m0 * (acc[mf][nf][1] + bb);
            float o2 = h8.x + m8 * (acc[mf][nf][2] + ba);
            float o3 = h8.y + m8 * (acc[mf][nf][3] + bb);
            *(float2*)&out[(size_t)rr * F + cc]       = make_float2(o0, o1);
            *(float2*)&out[(size_t)(rr + 8) * F + cc] = make_float2(o2, o3);
        }
    }
}

extern "C" void kernel_launch(void* const* d_in, const int* in_sizes, int n_in,
                              void* d_out, int out_size)
{
    const int*   z    = (const int*)d_in[0];
    const float* r    = (const float*)d_in[1];
    const float* h    = (const float*)d_in[2];
    const float* dist = (const float*)d_in[3];
    const float* wids = (const float*)d_in[4];
    const float* W1   = (const float*)d_in[5];
    const float* b1   = (const float*)d_in[6];
    const float* W2   = (const float*)d_in[7];
    const float* b2   = (const float*)d_in[8];

    __half *Uh, *Th, *hh, *W1h, *W2h;
    cudaGetSymbolAddress((void**)&Uh,  g_Uh);
    cudaGetSymbolAddress((void**)&Th,  g_Th);
    cudaGetSymbolAddress((void**)&hh,  g_hh);
    cudaGetSymbolAddress((void**)&W1h, g_W1h);
    cudaGetSymbolAddress((void**)&W2h, g_W2h);

    int nz = in_sizes[0], nr = in_sizes[1], nh = in_sizes[2];
    int nmol = nh / (MA * F);            // 512
    int rows = nmol * MA;                // 32768

    float* out   = (float*)d_out;
    float* out_h = out;
    if (out_size == nz + nr + nh) {
        k0_copy<<<(nr + 255) / 256, 256>>>(z, r, out, out + nz, nz, nr);
        out_h = out + nz + nr;
    }

    int ncvt = nh + DIN * HID + HID * F;
    kcvt_all<<<(ncvt / 4 + 255) / 256, 256>>>(h, W1, W2, hh, W1h, W2h, nh);

    k1_tc<<<nmol, 256>>>(z, r, dist, wids, hh, Uh);

    cudaFuncSetAttribute(k2_tc, cudaFuncAttributeMaxDynamicSharedMemorySize, K2_DYN);
    k2_tc<<<dim3(HID / 256, rows / 128), 256, K2_DYN>>>(hh, Uh, W1h, b1, Th);

    cudaFuncSetAttribute(k3_tc, cudaFuncAttributeMaxDynamicSharedMemorySize, K3_DYN);
    k3_tc<<<rows / 128, 256, K3_DYN>>>(Th, W2h, b2, h, z, out_h);
}

// round 11
// speedup vs baseline: 6.4945x; 1.0382x over previous
#include <cuda_runtime.h>
#include <cuda_fp16.h>
#include <cstdint>

typedef unsigned long long ull;

#define NMOL 512
#define MA   64
#define F    128
#define NF   16
#define DIN  2176   // F*(1+NF)
#define HID  512

// ======================= helpers =======================
__device__ __forceinline__ uint32_t smem_to_u32(const void* p) {
    uint32_t a;
    asm("{ .reg .u64 t; cvta.to.shared.u64 t, %1; cvt.u32.u64 %0, t; }" : "=r"(a) : "l"(p));
    return a;
}
__device__ __forceinline__ void cpasync16(uint32_t s, const void* g) {
    asm volatile("cp.async.cg.shared.global [%0], [%1], 16;" :: "r"(s), "l"(g) : "memory");
}
__device__ __forceinline__ void cp_commit() { asm volatile("cp.async.commit_group;" ::: "memory"); }
__device__ __forceinline__ void cp_wait2()  { asm volatile("cp.async.wait_group 2;"  ::: "memory"); }
__device__ __forceinline__ void cp_wait1()  { asm volatile("cp.async.wait_group 1;"  ::: "memory"); }
__device__ __forceinline__ void cp_wait0()  { asm volatile("cp.async.wait_group 0;"  ::: "memory"); }

__device__ __forceinline__ void ld4(uint32_t& r0, uint32_t& r1, uint32_t& r2, uint32_t& r3, uint32_t a) {
    asm volatile("ldmatrix.sync.aligned.m8n8.x4.shared.b16 {%0,%1,%2,%3}, [%4];"
                 : "=r"(r0), "=r"(r1), "=r"(r2), "=r"(r3) : "r"(a));
}
__device__ __forceinline__ void ld4t(uint32_t& r0, uint32_t& r1, uint32_t& r2, uint32_t& r3, uint32_t a) {
    asm volatile("ldmatrix.sync.aligned.m8n8.x4.trans.shared.b16 {%0,%1,%2,%3}, [%4];"
                 : "=r"(r0), "=r"(r1), "=r"(r2), "=r"(r3) : "r"(a));
}
// f16 MMA, f32 accumulate: m16n8k16
__device__ __forceinline__ void mma16(float& c0, float& c1, float& c2, float& c3,
                                      uint32_t a0, uint32_t a1, uint32_t a2, uint32_t a3,
                                      uint32_t b0, uint32_t b1) {
    asm volatile("mma.sync.aligned.m16n8k16.row.col.f32.f16.f16.f32 "
                 "{%0,%1,%2,%3}, {%4,%5,%6,%7}, {%8,%9}, {%0,%1,%2,%3};"
                 : "+f"(c0), "+f"(c1), "+f"(c2), "+f"(c3)
                 : "r"(a0), "r"(a1), "r"(a2), "r"(a3), "r"(b0), "r"(b1));
}
__device__ __forceinline__ uint32_t h2u(__half2 h) { return *(uint32_t*)&h; }

// ---------- scratch (device globals: allocation-free) ----------
__device__ __align__(256) __half g_Uh[(size_t)NMOL * MA * NF * F];   // 134 MB
__device__ __align__(256) __half g_Th[(size_t)NMOL * MA * HID];      // 32 MB
__device__ __align__(256) __half g_hh[(size_t)NMOL * MA * F];        // 8 MB
__device__ __align__(256) __half g_W1h[(size_t)DIN * HID];           // 2.2 MB  (k-major, as W1)
__device__ __align__(256) __half g_W2h[(size_t)HID * F];             // 128 KB  (k-major, as W2)

// ---------- K0: copy z (as float) and r into the output buffer ----------
__global__ void k0_copy(const int* __restrict__ z, const float* __restrict__ r,
                        float* __restrict__ oz, float* __restrict__ orr,
                        int nz, int nr) {
    int i = blockIdx.x * blockDim.x + threadIdx.x;
    if (i < nz) oz[i]  = (float)z[i];
    if (i < nr) orr[i] = r[i];
}

// ---------- f32 -> f16 (RNE) convert: h, W1, W2 in one launch ----------
__global__ void kcvt_all(const float* __restrict__ h,  const float* __restrict__ W1,
                         const float* __restrict__ W2, __half* __restrict__ hh,
                         __half* __restrict__ W1h, __half* __restrict__ W2h, int nh)
{
    const int n1 = DIN * HID, n2 = HID * F;
    int i = (blockIdx.x * blockDim.x + threadIdx.x) * 4;
    const float* s; __half* d; int off;
    if (i < nh)                { s = h;  d = hh;  off = 0; }
    else if (i < nh + n1)      { s = W1; d = W1h; off = nh; }
    else if (i < nh + n1 + n2) { s = W2; d = W2h; off = nh + n1; }
    else return;
    int j = i - off;
    float4 v = *(const float4*)(s + j);
    __half2 a = __floats2half2_rn(v.x, v.y);
    __half2 b = __floats2half2_rn(v.z, v.w);
    *(uint2*)(d + j) = make_uint2(h2u(a), h2u(b));
}

// ======================= K1: RBF + aggregation on tensor cores =======================
__global__ __launch_bounds__(256) void k1_tc(
    const int* __restrict__ z, const float* __restrict__ r,
    const float* __restrict__ dist, const float* __restrict__ widths,
    const __half* __restrict__ hh, __half* __restrict__ U)
{
    __shared__ __half sh_h[MA * F];   // 16 KB, swizzled k-major (256B rows)
    __shared__ __half sh_w[MA * MA];  // 8 KB, swizzled row-major (128B rows)
    __shared__ float s_r[192];
    __shared__ float s_m[64];
    int n = blockIdx.x, tid = threadIdx.x;
    int wid = tid >> 5, lane = tid & 31;
    int gid = lane >> 2, tig = lane & 3;
    int warp_m = wid >> 1, warp_n = wid & 1;
    uint32_t hbase = smem_to_u32(sh_h), wbase = smem_to_u32(sh_w);

    {
        const __half* hg = hh + (size_t)n * MA * F;
#pragma unroll
        for (int p = 0; p < 4; p++) {
            int idx = p * 256 + tid;
            int row = idx >> 4, u = idx & 15;
            cpasync16(hbase + row * 256 + ((u ^ (row & 7)) << 4), hg + (size_t)row * F + u * 8);
        }
        cp_commit();
    }
    if (tid < 192) s_r[tid] = r[(size_t)n * 192 + tid];
    if (tid >= 192) s_m[tid - 192] = (z[n * MA + (tid - 192)] > -1) ? 1.0f : 0.0f;
    __syncthreads();

    float d[16];
    {
        int b = tid & 63;
        float bx = s_r[b * 3 + 0], by = s_r[b * 3 + 1], bz = s_r[b * 3 + 2];
        float mb = s_m[b];
#pragma unroll
        for (int q = 0; q < 16; q++) {
            int a = (tid >> 6) + 4 * q;
            float dx = s_r[a * 3 + 0] - bx;
            float dy = s_r[a * 3 + 1] - by;
            float dz = s_r[a * 3 + 2] - bz;
            float dd = sqrtf(dx * dx + dy * dy + dz * dz + 1e-12f);
            if (s_m[a] * mb == 0.0f) dd = 1e9f;
            d[q] = dd;
        }
    }

    int aRow = warp_m * 16 + (lane & 15);
    int aSw  = lane & 7;
    int kuHi = (lane >> 4);
    int bKrl = (lane & 7) + ((lane >> 3) & 1) * 8;
    int bNuL = (lane >> 4);
    int wb   = tid & 63;
    __half* Un = U + (size_t)n * MA * (NF * F);

    for (int f = 0; f < NF; f++) {
        float mu   = __ldg(&dist[f]);
        float isg2 = 1.4426950408889634f / __ldg(&widths[f]);
        __syncthreads();
#pragma unroll
        for (int q = 0; q < 16; q++) {
            int a = (tid >> 6) + 4 * q;
            float t = d[q] - mu;
            __half wv = __float2half_rn(5.0f * exp2f(-t * t * isg2));
            int off = a * 128 + ((((wb >> 3) ^ (a & 7))) << 4) + (wb & 7) * 2;
            *(__half*)((char*)sh_w + off) = wv;
        }
        if (f == 0) cp_wait0();
        __syncthreads();

        float acc[8][4];
#pragma unroll
        for (int nf = 0; nf < 8; nf++)
#pragma unroll
            for (int q = 0; q < 4; q++) acc[nf][q] = 0.0f;

#pragma unroll
        for (int kk = 0; kk < 4; kk++) {
            uint32_t a0, a1, a2, a3;
            uint32_t ad = wbase + aRow * 128 + (((kk * 2 + kuHi) ^ aSw) << 4);
            ld4(a0, a1, a2, a3, ad);
#pragma unroll
            for (int np = 0; np < 4; np++) {
                int krow = kk * 16 + bKrl;
                int nu = warp_n * 8 + np * 2 + bNuL;
                uint32_t bd = hbase + krow * 256 + ((nu ^ (krow & 7)) << 4);
                uint32_t b0, b1r, b2, b3;
                ld4t(b0, b1r, b2, b3, bd);
                int nf0 = np * 2, nf1 = nf0 + 1;
                mma16(acc[nf0][0], acc[nf0][1], acc[nf0][2], acc[nf0][3],
                      a0, a1, a2, a3, b0, b1r);
                mma16(acc[nf1][0], acc[nf1][1], acc[nf1][2], acc[nf1][3],
                      a0, a1, a2, a3, b2, b3);
            }
        }
        int rr = warp_m * 16 + gid;
#pragma unroll
        for (int nf = 0; nf < 8; nf++) {
            int cc = warp_n * 64 + nf * 8 + tig * 2;
            *(uint32_t*)&Un[(size_t)rr * (NF * F) + f * F + cc] =
                h2u(__floats2half2_rn(acc[nf][0], acc[nf][1]));
            *(uint32_t*)&Un[(size_t)(rr + 8) * (NF * F) + f * F + cc] =
                h2u(__floats2half2_rn(acc[nf][2], acc[nf][3]));
        }
    }
}

// ======================= K2: T = silu([h|U] @ W1 + b1) via f16 mma =======================
// BM=128, BN=256, BK=64 halves, 3-stage cp.async.
// 512 threads = 16 warps as 4(m) x 4(n); warp tile 32x64 -> 64 acc regs/thread,
// 4 warps/SMSP for latency hiding (round-9 ncu: tensor=50.6% at 2 warps/SMSP).
#define K2_CHUNKS 34
#define K2_A_BYTES 16384
#define K2_B_BYTES 32768
#define K2_STAGE   (K2_A_BYTES + K2_B_BYTES)   // 49152
#define K2_DYN     (3 * K2_STAGE)              // 147456

__device__ __forceinline__ void k2_load(int j, int row0, int col0,
    const __half* __restrict__ hh, const __half* __restrict__ Uh,
    const __half* __restrict__ W1h, uint32_t sA, uint32_t sB, int tid)
{
    int k0 = j * 64;
    const __half* Ab; size_t lda;
    if (k0 < F) { Ab = hh + (size_t)row0 * F + k0;          lda = F; }
    else        { Ab = Uh + (size_t)row0 * 2048 + (k0 - F); lda = 2048; }
#pragma unroll
    for (int p = 0; p < 2; p++) {
        int idx = p * 512 + tid;
        int m = idx >> 3, u = idx & 7;
        cpasync16(sA + m * 128 + (((u ^ (m & 7))) << 4), Ab + (size_t)m * lda + u * 8);
    }
    const __half* Bb = W1h + (size_t)k0 * HID + col0;
#pragma unroll
    for (int p = 0; p < 4; p++) {
        int idx = p * 512 + tid;
        int kr = idx >> 5, u = idx & 31;
        cpasync16(sB + kr * 512 + (((u ^ (kr & 7))) << 4), Bb + (size_t)kr * HID + u * 8);
    }
}

__global__ __launch_bounds__(512, 1) void k2_tc(
    const __half* __restrict__ hh, const __half* __restrict__ Uh,
    const __half* __restrict__ W1h, const float* __restrict__ b1,
    __half* __restrict__ T)
{
    extern __shared__ char dynsm[];
    uint32_t dbase = smem_to_u32(dynsm);
    int tid = threadIdx.x, wid = tid >> 5, lane = tid & 31;
    int gid = lane >> 2, tig = lane & 3;
    int warp_m = wid >> 2, warp_n = wid & 3;     // 4 x 4 warps
    int col0 = blockIdx.x * 256, row0 = blockIdx.y * 128;

    float acc[2][8][4];
#pragma unroll
    for (int mf = 0; mf < 2; mf++)
#pragma unroll
        for (int nf = 0; nf < 8; nf++)
#pragma unroll
            for (int q = 0; q < 4; q++) acc[mf][nf][q] = 0.0f;

    int aRow = warp_m * 32 + (lane & 15);        // + mf*16
    int aSw  = lane & 7;
    int kuHi = (lane >> 4);
    int bKrl = (lane & 7) + ((lane >> 3) & 1) * 8;
    int bNuL = (lane >> 4);

#pragma unroll
    for (int s = 0; s < 2; s++) {
        k2_load(s, row0, col0, hh, Uh, W1h, dbase + s * K2_STAGE, dbase + s * K2_STAGE + K2_A_BYTES, tid);
        cp_commit();
    }

    for (int j = 0; j < K2_CHUNKS; j++) {
        int s = j % 3;
        if (j < K2_CHUNKS - 1) cp_wait1(); else cp_wait0();
        __syncthreads();
        if (j + 2 < K2_CHUNKS) {
            int s2 = (j + 2) % 3;
            k2_load(j + 2, row0, col0, hh, Uh, W1h,
                    dbase + s2 * K2_STAGE, dbase + s2 * K2_STAGE + K2_A_BYTES, tid);
            cp_commit();
        }
        uint32_t sA = dbase + s * K2_STAGE;
        uint32_t sB = sA + K2_A_BYTES;
#pragma unroll
        for (int kk = 0; kk < 4; kk++) {
            uint32_t a[2][4];
#pragma unroll
            for (int mf = 0; mf < 2; mf++) {
                int rowm = aRow + mf * 16;
                uint32_t ad = sA + rowm * 128 + (((kk * 2 + kuHi) ^ aSw) << 4);
                ld4(a[mf][0], a[mf][1], a[mf][2], a[mf][3], ad);
            }
#pragma unroll
            for (int np = 0; np < 4; np++) {
                int krow = kk * 16 + bKrl;
                int nu = warp_n * 8 + np * 2 + bNuL;
                uint32_t bd = sB + krow * 512 + (((nu ^ (krow & 7))) << 4);
                uint32_t b0, b1r, b2, b3;
                ld4t(b0, b1r, b2, b3, bd);
                int nf0 = np * 2, nf1 = nf0 + 1;
#pragma unroll
                for (int mf = 0; mf < 2; mf++) {
                    mma16(acc[mf][nf0][0], acc[mf][nf0][1], acc[mf][nf0][2], acc[mf][nf0][3],
                          a[mf][0], a[mf][1], a[mf][2], a[mf][3], b0, b1r);
                    mma16(acc[mf][nf1][0], acc[mf][nf1][1], acc[mf][nf1][2], acc[mf][nf1][3],
                          a[mf][0], a[mf][1], a[mf][2], a[mf][3], b2, b3);
                }
            }
        }
        __syncthreads();
    }

    // epilogue: bias + silu -> T (half)
#pragma unroll
    for (int mf = 0; mf < 2; mf++) {
        int rr = row0 + warp_m * 32 + mf * 16 + gid;
#pragma unroll
        for (int nf = 0; nf < 8; nf++) {
            int cc = col0 + warp_n * 64 + nf * 8 + tig * 2;
            float ba = __ldg(&b1[cc]), bb = __ldg(&b1[cc + 1]);
            float x0 = acc[mf][nf][0] + ba, x1 = acc[mf][nf][1] + bb;
            float x2 = acc[mf][nf][2] + ba, x3 = acc[mf][nf][3] + bb;
            x0 = x0 / (1.0f + __expf(-x0));
            x1 = x1 / (1.0f + __expf(-x1));
            x2 = x2 / (1.0f + __expf(-x2));
            x3 = x3 / (1.0f + __expf(-x3));
            *(uint32_t*)&T[(size_t)rr * HID + cc]       = h2u(__floats2half2_rn(x0, x1));
            *(uint32_t*)&T[(size_t)(rr + 8) * HID + cc] = h2u(__floats2half2_rn(x2, x3));
        }
    }
}

// ======================= K3: out = h + 0.1*(T @ W2 + b2)*mask via f16 mma =======================
#define K3_CHUNKS 8
#define K3_A_BYTES 16384
#define K3_B_BYTES 16384
#define K3_STAGE   (K3_A_BYTES + K3_B_BYTES)
#define K3_DYN     (3 * K3_STAGE)

__device__ __forceinline__ void k3_load(int j, int row0,
    const __half* __restrict__ T, const __half* __restrict__ W2h,
    uint32_t sA, uint32_t sB, int tid)
{
    int k0 = j * 64;
    const __half* Ab = T + (size_t)row0 * HID + k0;
#pragma unroll
    for (int p = 0; p < 4; p++) {
        int idx = p * 256 + tid;
        int m = idx >> 3, u = idx & 7;
        cpasync16(sA + m * 128 + (((u ^ (m & 7))) << 4), Ab + (size_t)m * HID + u * 8);
    }
    const __half* Bb = W2h + (size_t)k0 * F;
#pragma unroll
    for (int p = 0; p < 4; p++) {
        int idx = p * 256 + tid;
        int kr = idx >> 4, u = idx & 15;
        cpasync16(sB + kr * 256 + (((u ^ (kr & 7))) << 4), Bb + (size_t)kr * F + u * 8);
    }
}

__global__ __launch_bounds__(256, 1) void k3_tc(
    const __half* __restrict__ T, const __half* __restrict__ W2h,
    const float* __restrict__ b2, const float* __restrict__ h,
    const int* __restrict__ z, float* __restrict__ out)
{
    extern __shared__ char dynsm[];
    uint32_t dbase = smem_to_u32(dynsm);
    int tid = threadIdx.x, wid = tid >> 5, lane = tid & 31;
    int gid = lane >> 2, tig = lane & 3;
    int warp_m = wid >> 2, warp_n = wid & 3;
    int row0 = blockIdx.x * 128;

    float acc[4][4][4];
#pragma unroll
    for (int mf = 0; mf < 4; mf++)
#pragma unroll
        for (int nf = 0; nf < 4; nf++)
#pragma unroll
            for (int q = 0; q < 4; q++) acc[mf][nf][q] = 0.0f;

    int aRow = warp_m * 64 + (lane & 15);
    int aSw  = lane & 7;
    int kuHi = (lane >> 4);
    int bKrl = (lane & 7) + ((lane >> 3) & 1) * 8;
    int bNuL = (lane >> 4);

    k3_load(0, row0, T, W2h, dbase, dbase + K3_A_BYTES, tid);
    cp_commit();
    k3_load(1, row0, T, W2h, dbase + K3_STAGE, dbase + K3_STAGE + K3_A_BYTES, tid);
    cp_commit();

    for (int j = 0; j < K3_CHUNKS; j++) {
        int s = j % 3;
        if (j < K3_CHUNKS - 1) cp_wait1(); else cp_wait0();
        __syncthreads();
        if (j + 2 < K3_CHUNKS) {
            int s2 = (j + 2) % 3;
            k3_load(j + 2, row0, T, W2h,
                    dbase + s2 * K3_STAGE, dbase + s2 * K3_STAGE + K3_A_BYTES, tid);
            cp_commit();
        }
        uint32_t sA = dbase + s * K3_STAGE;
        uint32_t sB = sA + K3_A_BYTES;
#pragma unroll
        for (int kk = 0; kk < 4; kk++) {
            uint32_t a[4][4];
#pragma unroll
            for (int mf = 0; mf < 4; mf++) {
                int rowm = aRow + mf * 16;
                uint32_t ad = sA + rowm * 128 + (((kk * 2 + kuHi) ^ aSw) << 4);
                ld4(a[mf][0], a[mf][1], a[mf][2], a[mf][3], ad);
            }
#pragma unroll
            for (int np = 0; np < 2; np++) {
                int krow = kk * 16 + bKrl;
                int nu = warp_n * 4 + np * 2 + bNuL;
                uint32_t bd = sB + krow * 256 + (((nu ^ (krow & 7))) << 4);
                uint32_t b0, b1r, b2, b3;
                ld4t(b0, b1r, b2, b3, bd);
                int nf0 = np * 2, nf1 = nf0 + 1;
#pragma unroll
                for (int mf = 0; mf < 4; mf++) {
                    mma16(acc[mf][nf0][0], acc[mf][nf0][1], acc[mf][nf0][2], acc[mf][nf0][3],
                          a[mf][0], a[mf][1], a[mf][2], a[mf][3], b0, b1r);
                    mma16(acc[mf][nf1][0], acc[mf][nf1][1], acc[mf][nf1][2], acc[mf][nf1][3],
                          a[mf][0], a[mf][1], a[mf][2], a[mf][3], b2, b3);
                }
            }
        }
        __syncthreads();
    }

#pragma unroll
    for (int mf = 0; mf < 4; mf++) {
        int rr = row0 + warp_m * 64 + mf * 16 + gid;
        float m0 = (__ldg(&z[rr])     > -1) ? 0.1f : 0.0f;
        float m8 = (__ldg(&z[rr + 8]) > -1) ? 0.1f : 0.0f;
#pragma unroll
        for (int nf = 0; nf < 4; nf++) {
            int cc = warp_n * 32 + nf * 8 + tig * 2;
            float ba = __ldg(&b2[cc]), bb = __ldg(&b2[cc + 1]);
            float2 h0 = *(const float2*)&h[(size_t)rr * F + cc];
            float2 h8 = *(const float2*)&h[(size_t)(rr + 8) * F + cc];
            float o0 = h0.x + m0 * (acc[mf][nf][0] + ba);
            float o1 = h0.y + m0 * (acc[mf][nf][1] + bb);
            float o2 = h8.x + m8 * (acc[mf][nf][2] + ba);
            float o3 = h8.y + m8 * (acc[mf][nf][3] + bb);
            *(float2*)&out[(size_t)rr * F + cc]       = make_float2(o0, o1);
            *(float2*)&out[(size_t)(rr + 8) * F + cc] = make_float2(o2, o3);
        }
    }
}

extern "C" void kernel_launch(void* const* d_in, const int* in_sizes, int n_in,
                              void* d_out, int out_size)
{
    const int*   z    = (const int*)d_in[0];
    const float* r    = (const float*)d_in[1];
    const float* h    = (const float*)d_in[2];
    const float* dist = (const float*)d_in[3];
    const float* wids = (const float*)d_in[4];
    const float* W1   = (const float*)d_in[5];
    const float* b1   = (const float*)d_in[6];
    const float* W2   = (const float*)d_in[7];
    const float* b2   = (const float*)d_in[8];

    __half *Uh, *Th, *hh, *W1h, *W2h;
    cudaGetSymbolAddress((void**)&Uh,  g_Uh);
    cudaGetSymbolAddress((void**)&Th,  g_Th);
    cudaGetSymbolAddress((void**)&hh,  g_hh);
    cudaGetSymbolAddress((void**)&W1h, g_W1h);
    cudaGetSymbolAddress((void**)&W2h, g_W2h);

    int nz = in_sizes[0], nr = in_sizes[1], nh = in_sizes[2];
    int nmol = nh / (MA * F);            // 512
    int rows = nmol * MA;                // 32768

    float* out   = (float*)d_out;
    float* out_h = out;
    if (out_size == nz + nr + nh) {
        k0_copy<<<(nr + 255) / 256, 256>>>(z, r, out, out + nz, nz, nr);
        out_h = out + nz + nr;
    }

    int ncvt = nh + DIN * HID + HID * F;
    kcvt_all<<<(ncvt / 4 + 255) / 256, 256>>>(h, W1, W2, hh, W1h, W2h, nh);

    k1_tc<<<nmol, 256>>>(z, r, dist, wids, hh, Uh);

    cudaFuncSetAttribute(k2_tc, cudaFuncAttributeMaxDynamicSharedMemorySize, K2_DYN);
    k2_tc<<<dim3(HID / 256, rows / 128), 512, K2_DYN>>>(hh, Uh, W1h, b1, Th);

    cudaFuncSetAttribute(k3_tc, cudaFuncAttributeMaxDynamicSharedMemorySize, K3_DYN);
    k3_tc<<<rows / 128, 256, K3_DYN>>>(Th, W2h, b2, h, z, out_h);
}

// round 12
// speedup vs baseline: 6.7289x; 1.0361x over previous
#include <cuda_runtime.h>
#include <cuda_fp16.h>
#include <cstdint>

typedef unsigned long long ull;

#define NMOL 512
#define MA   64
#define F    128
#define NF   16
#define DIN  2176   // F*(1+NF)
#define HID  512

// ======================= helpers =======================
__device__ __forceinline__ uint32_t smem_to_u32(const void* p) {
    uint32_t a;
    asm("{ .reg .u64 t; cvta.to.shared.u64 t, %1; cvt.u32.u64 %0, t; }" : "=r"(a) : "l"(p));
    return a;
}
__device__ __forceinline__ void cpasync16(uint32_t s, const void* g) {
    asm volatile("cp.async.cg.shared.global [%0], [%1], 16;" :: "r"(s), "l"(g) : "memory");
}
__device__ __forceinline__ void cp_commit() { asm volatile("cp.async.commit_group;" ::: "memory"); }
__device__ __forceinline__ void cp_wait0()  { asm volatile("cp.async.wait_group 0;"  ::: "memory"); }

__device__ __forceinline__ void ld4(uint32_t& r0, uint32_t& r1, uint32_t& r2, uint32_t& r3, uint32_t a) {
    asm volatile("ldmatrix.sync.aligned.m8n8.x4.shared.b16 {%0,%1,%2,%3}, [%4];"
                 : "=r"(r0), "=r"(r1), "=r"(r2), "=r"(r3) : "r"(a));
}
__device__ __forceinline__ void ld4t(uint32_t& r0, uint32_t& r1, uint32_t& r2, uint32_t& r3, uint32_t a) {
    asm volatile("ldmatrix.sync.aligned.m8n8.x4.trans.shared.b16 {%0,%1,%2,%3}, [%4];"
                 : "=r"(r0), "=r"(r1), "=r"(r2), "=r"(r3) : "r"(a));
}
// f16 MMA, f32 accumulate: m16n8k16
__device__ __forceinline__ void mma16(float& c0, float& c1, float& c2, float& c3,
                                      uint32_t a0, uint32_t a1, uint32_t a2, uint32_t a3,
                                      uint32_t b0, uint32_t b1) {
    asm volatile("mma.sync.aligned.m16n8k16.row.col.f32.f16.f16.f32 "
                 "{%0,%1,%2,%3}, {%4,%5,%6,%7}, {%8,%9}, {%0,%1,%2,%3};"
                 : "+f"(c0), "+f"(c1), "+f"(c2), "+f"(c3)
                 : "r"(a0), "r"(a1), "r"(a2), "r"(a3), "r"(b0), "r"(b1));
}
__device__ __forceinline__ uint32_t h2u(__half2 h) { return *(uint32_t*)&h; }

// ---------- scratch (device globals: allocation-free) ----------
__device__ __align__(256) __half g_Uh[(size_t)NMOL * MA * NF * F];   // 134 MB
__device__ __align__(256) __half g_Th[(size_t)NMOL * MA * HID];      // 32 MB
__device__ __align__(256) __half g_hh[(size_t)NMOL * MA * F];        // 8 MB
__device__ __align__(256) __half g_W1h[(size_t)DIN * HID];           // 2.2 MB  (k-major, as W1)
__device__ __align__(256) __half g_W2h[(size_t)HID * F];             // 128 KB  (k-major, as W2)

// ---------- K0: copy z (as float) and r into the output buffer ----------
__global__ void k0_copy(const int* __restrict__ z, const float* __restrict__ r,
                        float* __restrict__ oz, float* __restrict__ orr,
                        int nz, int nr) {
    int i = blockIdx.x * blockDim.x + threadIdx.x;
    if (i < nz) oz[i]  = (float)z[i];
    if (i < nr) orr[i] = r[i];
}

// ---------- f32 -> f16 (RNE) convert: h, W1, W2 in one launch ----------
__global__ void kcvt_all(const float* __restrict__ h,  const float* __restrict__ W1,
                         const float* __restrict__ W2, __half* __restrict__ hh,
                         __half* __restrict__ W1h, __half* __restrict__ W2h, int nh)
{
    const int n1 = DIN * HID, n2 = HID * F;
    int i = (blockIdx.x * blockDim.x + threadIdx.x) * 4;
    const float* s; __half* d; int off;
    if (i < nh)                { s = h;  d = hh;  off = 0; }
    else if (i < nh + n1)      { s = W1; d = W1h; off = nh; }
    else if (i < nh + n1 + n2) { s = W2; d = W2h; off = nh + n1; }
    else return;
    int j = i - off;
    float4 v = *(const float4*)(s + j);
    __half2 a = __floats2half2_rn(v.x, v.y);
    __half2 b = __floats2half2_rn(v.z, v.w);
    *(uint2*)(d + j) = make_uint2(h2u(a), h2u(b));
}

// ======================= K1: RBF + aggregation on tensor cores =======================
__global__ __launch_bounds__(256) void k1_tc(
    const int* __restrict__ z, const float* __restrict__ r,
    const float* __restrict__ dist, const float* __restrict__ widths,
    const __half* __restrict__ hh, __half* __restrict__ U)
{
    __shared__ __half sh_h[MA * F];   // 16 KB, swizzled k-major (256B rows)
    __shared__ __half sh_w[MA * MA];  // 8 KB, swizzled row-major (128B rows)
    __shared__ float s_r[192];
    __shared__ float s_m[64];
    int n = blockIdx.x, tid = threadIdx.x;
    int wid = tid >> 5, lane = tid & 31;
    int gid = lane >> 2, tig = lane & 3;
    int warp_m = wid >> 1, warp_n = wid & 1;
    uint32_t hbase = smem_to_u32(sh_h), wbase = smem_to_u32(sh_w);

    {
        const __half* hg = hh + (size_t)n * MA * F;
#pragma unroll
        for (int p = 0; p < 4; p++) {
            int idx = p * 256 + tid;
            int row = idx >> 4, u = idx & 15;
            cpasync16(hbase + row * 256 + ((u ^ (row & 7)) << 4), hg + (size_t)row * F + u * 8);
        }
        cp_commit();
    }
    if (tid < 192) s_r[tid] = r[(size_t)n * 192 + tid];
    if (tid >= 192) s_m[tid - 192] = (z[n * MA + (tid - 192)] > -1) ? 1.0f : 0.0f;
    __syncthreads();

    float d[16];
    {
        int b = tid & 63;
        float bx = s_r[b * 3 + 0], by = s_r[b * 3 + 1], bz = s_r[b * 3 + 2];
        float mb = s_m[b];
#pragma unroll
        for (int q = 0; q < 16; q++) {
            int a = (tid >> 6) + 4 * q;
            float dx = s_r[a * 3 + 0] - bx;
            float dy = s_r[a * 3 + 1] - by;
            float dz = s_r[a * 3 + 2] - bz;
            float dd = sqrtf(dx * dx + dy * dy + dz * dz + 1e-12f);
            if (s_m[a] * mb == 0.0f) dd = 1e9f;
            d[q] = dd;
        }
    }

    int aRow = warp_m * 16 + (lane & 15);
    int aSw  = lane & 7;
    int kuHi = (lane >> 4);
    int bKrl = (lane & 7) + ((lane >> 3) & 1) * 8;
    int bNuL = (lane >> 4);
    int wb   = tid & 63;
    __half* Un = U + (size_t)n * MA * (NF * F);

    for (int f = 0; f < NF; f++) {
        float mu   = __ldg(&dist[f]);
        float isg2 = 1.4426950408889634f / __ldg(&widths[f]);
        __syncthreads();
#pragma unroll
        for (int q = 0; q < 16; q++) {
            int a = (tid >> 6) + 4 * q;
            float t = d[q] - mu;
            __half wv = __float2half_rn(5.0f * exp2f(-t * t * isg2));
            int off = a * 128 + ((((wb >> 3) ^ (a & 7))) << 4) + (wb & 7) * 2;
            *(__half*)((char*)sh_w + off) = wv;
        }
        if (f == 0) cp_wait0();
        __syncthreads();

        float acc[8][4];
#pragma unroll
        for (int nf = 0; nf < 8; nf++)
#pragma unroll
            for (int q = 0; q < 4; q++) acc[nf][q] = 0.0f;

#pragma unroll
        for (int kk = 0; kk < 4; kk++) {
            uint32_t a0, a1, a2, a3;
            uint32_t ad = wbase + aRow * 128 + (((kk * 2 + kuHi) ^ aSw) << 4);
            ld4(a0, a1, a2, a3, ad);
#pragma unroll
            for (int np = 0; np < 4; np++) {
                int krow = kk * 16 + bKrl;
                int nu = warp_n * 8 + np * 2 + bNuL;
                uint32_t bd = hbase + krow * 256 + ((nu ^ (krow & 7)) << 4);
                uint32_t b0, b1r, b2, b3;
                ld4t(b0, b1r, b2, b3, bd);
                int nf0 = np * 2, nf1 = nf0 + 1;
                mma16(acc[nf0][0], acc[nf0][1], acc[nf0][2], acc[nf0][3],
                      a0, a1, a2, a3, b0, b1r);
                mma16(acc[nf1][0], acc[nf1][1], acc[nf1][2], acc[nf1][3],
                      a0, a1, a2, a3, b2, b3);
            }
        }
        int rr = warp_m * 16 + gid;
#pragma unroll
        for (int nf = 0; nf < 8; nf++) {
            int cc = warp_n * 64 + nf * 8 + tig * 2;
            *(uint32_t*)&Un[(size_t)rr * (NF * F) + f * F + cc] =
                h2u(__floats2half2_rn(acc[nf][0], acc[nf][1]));
            *(uint32_t*)&Un[(size_t)(rr + 8) * (NF * F) + f * F + cc] =
                h2u(__floats2half2_rn(acc[nf][2], acc[nf][3]));
        }
    }
}

// ======================= K2: T = silu([h|U] @ W1 + b1) via f16 mma =======================
// BM=128, BN=256, BK=128 halves, 2-stage cp.async, ONE barrier per chunk.
// 512 threads = 16 warps as 4(m) x 4(n); warp tile 32x64.
// A smem: 128 rows x 256B swizzled; B smem: 128 k-rows x 512B swizzled.
#define K2_CHUNKS 17
#define K2_A_BYTES 32768
#define K2_B_BYTES 65536
#define K2_STAGE   (K2_A_BYTES + K2_B_BYTES)   // 98304
#define K2_DYN     (2 * K2_STAGE)              // 196608

__device__ __forceinline__ void k2_load(int j, int row0, int col0,
    const __half* __restrict__ hh, const __half* __restrict__ Uh,
    const __half* __restrict__ W1h, uint32_t sA, uint32_t sB, int tid)
{
    int k0 = j * 128;
    const __half* Ab; size_t lda;
    if (j == 0) { Ab = hh + (size_t)row0 * F;                lda = F; }
    else        { Ab = Uh + (size_t)row0 * 2048 + (k0 - F);  lda = 2048; }
    // A: 128 rows x 128 halves (256B rows)
#pragma unroll
    for (int p = 0; p < 4; p++) {
        int idx = p * 512 + tid;
        int m = idx >> 4, u = idx & 15;
        cpasync16(sA + m * 256 + (((u ^ (m & 7))) << 4), Ab + (size_t)m * lda + u * 8);
    }
    // B: 128 k-rows x 256 halves (512B rows)
    const __half* Bb = W1h + (size_t)k0 * HID + col0;
#pragma unroll
    for (int p = 0; p < 8; p++) {
        int idx = p * 512 + tid;
        int kr = idx >> 5, u = idx & 31;
        cpasync16(sB + kr * 512 + (((u ^ (kr & 7))) << 4), Bb + (size_t)kr * HID + u * 8);
    }
}

__global__ __launch_bounds__(512, 1) void k2_tc(
    const __half* __restrict__ hh, const __half* __restrict__ Uh,
    const __half* __restrict__ W1h, const float* __restrict__ b1,
    __half* __restrict__ T)
{
    extern __shared__ char dynsm[];
    uint32_t dbase = smem_to_u32(dynsm);
    int tid = threadIdx.x, wid = tid >> 5, lane = tid & 31;
    int gid = lane >> 2, tig = lane & 3;
    int warp_m = wid >> 2, warp_n = wid & 3;     // 4 x 4 warps
    int col0 = blockIdx.x * 256, row0 = blockIdx.y * 128;

    float acc[2][8][4];
#pragma unroll
    for (int mf = 0; mf < 2; mf++)
#pragma unroll
        for (int nf = 0; nf < 8; nf++)
#pragma unroll
            for (int q = 0; q < 4; q++) acc[mf][nf][q] = 0.0f;

    int aRow = warp_m * 32 + (lane & 15);        // + mf*16
    int aSw  = lane & 7;
    int kuHi = (lane >> 4);
    int bKrl = (lane & 7) + ((lane >> 3) & 1) * 8;
    int bNuL = (lane >> 4);

    // prologue: stage 0
    k2_load(0, row0, col0, hh, Uh, W1h, dbase, dbase + K2_A_BYTES, tid);
    cp_commit();

    for (int j = 0; j < K2_CHUNKS; j++) {
        cp_wait0();          // stage j%2 data landed (only outstanding group)
        __syncthreads();     // + all warps done reading stage (j+1)%2 from iter j-1
        if (j + 1 < K2_CHUNKS) {
            uint32_t sN = dbase + ((j + 1) & 1) * K2_STAGE;
            k2_load(j + 1, row0, col0, hh, Uh, W1h, sN, sN + K2_A_BYTES, tid);
            cp_commit();     // overlaps with this chunk's mma
        }
        uint32_t sA = dbase + (j & 1) * K2_STAGE;
        uint32_t sB = sA + K2_A_BYTES;
#pragma unroll
        for (int kk = 0; kk < 8; kk++) {
            uint32_t a[2][4];
#pragma unroll
            for (int mf = 0; mf < 2; mf++) {
                int rowm = aRow + mf * 16;
                uint32_t ad = sA + rowm * 256 + (((kk * 2 + kuHi) ^ aSw) << 4);
                ld4(a[mf][0], a[mf][1], a[mf][2], a[mf][3], ad);
            }
#pragma unroll
            for (int np = 0; np < 4; np++) {
                int krow = kk * 16 + bKrl;
                int nu = warp_n * 8 + np * 2 + bNuL;
                uint32_t bd = sB + krow * 512 + (((nu ^ (krow & 7))) << 4);
                uint32_t b0, b1r, b2, b3;
                ld4t(b0, b1r, b2, b3, bd);
                int nf0 = np * 2, nf1 = nf0 + 1;
#pragma unroll
                for (int mf = 0; mf < 2; mf++) {
                    mma16(acc[mf][nf0][0], acc[mf][nf0][1], acc[mf][nf0][2], acc[mf][nf0][3],
                          a[mf][0], a[mf][1], a[mf][2], a[mf][3], b0, b1r);
                    mma16(acc[mf][nf1][0], acc[mf][nf1][1], acc[mf][nf1][2], acc[mf][nf1][3],
                          a[mf][0], a[mf][1], a[mf][2], a[mf][3], b2, b3);
                }
            }
        }
    }

    // epilogue: bias + silu -> T (half)
#pragma unroll
    for (int mf = 0; mf < 2; mf++) {
        int rr = row0 + warp_m * 32 + mf * 16 + gid;
#pragma unroll
        for (int nf = 0; nf < 8; nf++) {
            int cc = col0 + warp_n * 64 + nf * 8 + tig * 2;
            float ba = __ldg(&b1[cc]), bb = __ldg(&b1[cc + 1]);
            float x0 = acc[mf][nf][0] + ba, x1 = acc[mf][nf][1] + bb;
            float x2 = acc[mf][nf][2] + ba, x3 = acc[mf][nf][3] + bb;
            x0 = x0 / (1.0f + __expf(-x0));
            x1 = x1 / (1.0f + __expf(-x1));
            x2 = x2 / (1.0f + __expf(-x2));
            x3 = x3 / (1.0f + __expf(-x3));
            *(uint32_t*)&T[(size_t)rr * HID + cc]       = h2u(__floats2half2_rn(x0, x1));
            *(uint32_t*)&T[(size_t)(rr + 8) * HID + cc] = h2u(__floats2half2_rn(x2, x3));
        }
    }
}

// ======================= K3: out = h + 0.1*(T @ W2 + b2)*mask via f16 mma =======================
// BM=128, BN=128, BK=128, 2-stage, ONE barrier per chunk. 8 warps 2(m) x 4(n), warp 64x32.
#define K3_CHUNKS 4
#define K3_A_BYTES 32768
#define K3_B_BYTES 32768
#define K3_STAGE   (K3_A_BYTES + K3_B_BYTES)   // 65536
#define K3_DYN     (2 * K3_STAGE)              // 131072

__device__ __forceinline__ void k3_load(int j, int row0,
    const __half* __restrict__ T, const __half* __restrict__ W2h,
    uint32_t sA, uint32_t sB, int tid)
{
    int k0 = j * 128;
    const __half* Ab = T + (size_t)row0 * HID + k0;
#pragma unroll
    for (int p = 0; p < 8; p++) {
        int idx = p * 256 + tid;
        int m = idx >> 4, u = idx & 15;
        cpasync16(sA + m * 256 + (((u ^ (m & 7))) << 4), Ab + (size_t)m * HID + u * 8);
    }
    const __half* Bb = W2h + (size_t)k0 * F;
#pragma unroll
    for (int p = 0; p < 8; p++) {
        int idx = p * 256 + tid;
        int kr = idx >> 4, u = idx & 15;
        cpasync16(sB + kr * 256 + (((u ^ (kr & 7))) << 4), Bb + (size_t)kr * F + u * 8);
    }
}

__global__ __launch_bounds__(256, 1) void k3_tc(
    const __half* __restrict__ T, const __half* __restrict__ W2h,
    const float* __restrict__ b2, const float* __restrict__ h,
    const int* __restrict__ z, float* __restrict__ out)
{
    extern __shared__ char dynsm[];
    uint32_t dbase = smem_to_u32(dynsm);
    int tid = threadIdx.x, wid = tid >> 5, lane = tid & 31;
    int gid = lane >> 2, tig = lane & 3;
    int warp_m = wid >> 2, warp_n = wid & 3;
    int row0 = blockIdx.x * 128;

    float acc[4][4][4];
#pragma unroll
    for (int mf = 0; mf < 4; mf++)
#pragma unroll
        for (int nf = 0; nf < 4; nf++)
#pragma unroll
            for (int q = 0; q < 4; q++) acc[mf][nf][q] = 0.0f;

    int aRow = warp_m * 64 + (lane & 15);
    int aSw  = lane & 7;
    int kuHi = (lane >> 4);
    int bKrl = (lane & 7) + ((lane >> 3) & 1) * 8;
    int bNuL = (lane >> 4);

    k3_load(0, row0, T, W2h, dbase, dbase + K3_A_BYTES, tid);
    cp_commit();

    for (int j = 0; j < K3_CHUNKS; j++) {
        cp_wait0();
        __syncthreads();
        if (j + 1 < K3_CHUNKS) {
            uint32_t sN = dbase + ((j + 1) & 1) * K3_STAGE;
            k3_load(j + 1, row0, T, W2h, sN, sN + K3_A_BYTES, tid);
            cp_commit();
        }
        uint32_t sA = dbase + (j & 1) * K3_STAGE;
        uint32_t sB = sA + K3_A_BYTES;
#pragma unroll
        for (int kk = 0; kk < 8; kk++) {
            uint32_t a[4][4];
#pragma unroll
            for (int mf = 0; mf < 4; mf++) {
                int rowm = aRow + mf * 16;
                uint32_t ad = sA + rowm * 256 + (((kk * 2 + kuHi) ^ aSw) << 4);
                ld4(a[mf][0], a[mf][1], a[mf][2], a[mf][3], ad);
            }
#pragma unroll
            for (int np = 0; np < 2; np++) {
                int krow = kk * 16 + bKrl;
                int nu = warp_n * 4 + np * 2 + bNuL;
                uint32_t bd = sB + krow * 256 + (((nu ^ (krow & 7))) << 4);
                uint32_t b0, b1r, b2, b3;
                ld4t(b0, b1r, b2, b3, bd);
                int nf0 = np * 2, nf1 = nf0 + 1;
#pragma unroll
                for (int mf = 0; mf < 4; mf++) {
                    mma16(acc[mf][nf0][0], acc[mf][nf0][1], acc[mf][nf0][2], acc[mf][nf0][3],
                          a[mf][0], a[mf][1], a[mf][2], a[mf][3], b0, b1r);
                    mma16(acc[mf][nf1][0], acc[mf][nf1][1], acc[mf][nf1][2], acc[mf][nf1][3],
                          a[mf][0], a[mf][1], a[mf][2], a[mf][3], b2, b3);
                }
            }
        }
    }

#pragma unroll
    for (int mf = 0; mf < 4; mf++) {
        int rr = row0 + warp_m * 64 + mf * 16 + gid;
        float m0 = (__ldg(&z[rr])     > -1) ? 0.1f : 0.0f;
        float m8 = (__ldg(&z[rr + 8]) > -1) ? 0.1f : 0.0f;
#pragma unroll
        for (int nf = 0; nf < 4; nf++) {
            int cc = warp_n * 32 + nf * 8 + tig * 2;
            float ba = __ldg(&b2[cc]), bb = __ldg(&b2[cc + 1]);
            float2 h0 = *(const float2*)&h[(size_t)rr * F + cc];
            float2 h8 = *(const float2*)&h[(size_t)(rr + 8) * F + cc];
            float o0 = h0.x + m0 * (acc[mf][nf][0] + ba);
            float o1 = h0.y + m0 * (acc[mf][nf][1] + bb);
            float o2 = h8.x + m8 * (acc[mf][nf][2] + ba);
            float o3 = h8.y + m8 * (acc[mf][nf][3] + bb);
            *(float2*)&out[(size_t)rr * F + cc]       = make_float2(o0, o1);
            *(float2*)&out[(size_t)(rr + 8) * F + cc] = make_float2(o2, o3);
        }
    }
}

extern "C" void kernel_launch(void* const* d_in, const int* in_sizes, int n_in,
                              void* d_out, int out_size)
{
    const int*   z    = (const int*)d_in[0];
    const float* r    = (const float*)d_in[1];
    const float* h    = (const float*)d_in[2];
    const float* dist = (const float*)d_in[3];
    const float* wids = (const float*)d_in[4];
    const float* W1   = (const float*)d_in[5];
    const float* b1   = (const float*)d_in[6];
    const float* W2   = (const float*)d_in[7];
    const float* b2   = (const float*)d_in[8];

    __half *Uh, *Th, *hh, *W1h, *W2h;
    cudaGetSymbolAddress((void**)&Uh,  g_Uh);
    cudaGetSymbolAddress((void**)&Th,  g_Th);
    cudaGetSymbolAddress((void**)&hh,  g_hh);
    cudaGetSymbolAddress((void**)&W1h, g_W1h);
    cudaGetSymbolAddress((void**)&W2h, g_W2h);

    int nz = in_sizes[0], nr = in_sizes[1], nh = in_sizes[2];
    int nmol = nh / (MA * F);            // 512
    int rows = nmol * MA;                // 32768

    float* out   = (float*)d_out;
    float* out_h = out;
    if (out_size == nz + nr + nh) {
        k0_copy<<<(nr + 255) / 256, 256>>>(z, r, out, out + nz, nz, nr);
        out_h = out + nz + nr;
    }

    int ncvt = nh + DIN * HID + HID * F;
    kcvt_all<<<(ncvt / 4 + 255) / 256, 256>>>(h, W1, W2, hh, W1h, W2h, nh);

    k1_tc<<<nmol, 256>>>(z, r, dist, wids, hh, Uh);

    cudaFuncSetAttribute(k2_tc, cudaFuncAttributeMaxDynamicSharedMemorySize, K2_DYN);
    k2_tc<<<dim3(HID / 256, rows / 128), 512, K2_DYN>>>(hh, Uh, W1h, b1, Th);

    cudaFuncSetAttribute(k3_tc, cudaFuncAttributeMaxDynamicSharedMemorySize, K3_DYN);
    k3_tc<<<rows / 128, 256, K3_DYN>>>(Th, W2h, b2, h, z, out_h);
}